// round 1
// baseline (speedup 1.0000x reference)
#include <cuda_runtime.h>
#include <math_constants.h>

// Problem dims
#define BATCH   2
#define SEQ     4096
#define DMODEL  768
#define NHEADS  12
#define DHEAD   64
#define MTOT    (BATCH*SEQ)          // 8192

// Intermediate buffers, layout [B, H, S, Z]
__device__ float Qbuf[BATCH*NHEADS*SEQ*DHEAD];
__device__ float Kbuf[BATCH*NHEADS*SEQ*DHEAD];
__device__ float Vbuf[BATCH*NHEADS*SEQ*DHEAD];
__device__ float Zbuf[BATCH*NHEADS*SEQ*DHEAD];

// ---------------------------------------------------------------------------
// Kernel 1: fused QKV projection.
// grid.x = MTOT/64 (row tiles), grid.y = 36 (mat in {Q,K,V} x 12 heads)
// Each block computes a 64x64 output tile: 64 rows of x @ one head's [768,64] W.
// ---------------------------------------------------------------------------
__global__ __launch_bounds__(256) void qkv_proj_kernel(
    const float* __restrict__ x,
    const float* __restrict__ Wq, const float* __restrict__ Wk, const float* __restrict__ Wv,
    const float* __restrict__ bq, const float* __restrict__ bk, const float* __restrict__ bv)
{
    __shared__ float As[16][64];   // [k][m]
    __shared__ float Bs[16][64];   // [k][n]

    const int m0  = blockIdx.x * 64;
    const int y   = blockIdx.y;
    const int mat = y / NHEADS;
    const int h   = y % NHEADS;

    const float* W    = (mat == 0 ? Wq : (mat == 1 ? Wk : Wv)) + h * DMODEL * DHEAD;
    const float* bias = (mat == 0 ? bq : (mat == 1 ? bk : bv)) + h * DHEAD;
    float* Out        = (mat == 0 ? Qbuf : (mat == 1 ? Kbuf : Vbuf));

    const int tid = threadIdx.x;
    const int tx  = tid % 16;
    const int ty  = tid / 16;
    const int arow = tid / 4,  akq = tid % 4;   // A tile load: row 0..63, k-quad 0..3
    const int brow = tid / 16, bc4 = tid % 16;  // B tile load: k-row 0..15, col-quad 0..15

    float acc[4][4] = {};

    for (int k0 = 0; k0 < DMODEL; k0 += 16) {
        // Load A (x) 64x16 and transpose into As
        float4 av = *reinterpret_cast<const float4*>(x + (m0 + arow) * DMODEL + k0 + akq * 4);
        As[akq*4+0][arow] = av.x;
        As[akq*4+1][arow] = av.y;
        As[akq*4+2][arow] = av.z;
        As[akq*4+3][arow] = av.w;
        // Load B (W) 16x64
        *reinterpret_cast<float4*>(&Bs[brow][bc4*4]) =
            *reinterpret_cast<const float4*>(W + (k0 + brow) * DHEAD + bc4 * 4);
        __syncthreads();

        #pragma unroll
        for (int k = 0; k < 16; ++k) {
            float4 a = *reinterpret_cast<const float4*>(&As[k][ty*4]);
            float4 b = *reinterpret_cast<const float4*>(&Bs[k][tx*4]);
            acc[0][0] += a.x*b.x; acc[0][1] += a.x*b.y; acc[0][2] += a.x*b.z; acc[0][3] += a.x*b.w;
            acc[1][0] += a.y*b.x; acc[1][1] += a.y*b.y; acc[1][2] += a.y*b.z; acc[1][3] += a.y*b.w;
            acc[2][0] += a.z*b.x; acc[2][1] += a.z*b.y; acc[2][2] += a.z*b.z; acc[2][3] += a.z*b.w;
            acc[3][0] += a.w*b.x; acc[3][1] += a.w*b.y; acc[3][2] += a.w*b.z; acc[3][3] += a.w*b.w;
        }
        __syncthreads();
    }

    // Epilogue: write to [B,H,S,Z] with bias
    float4 bias4 = *reinterpret_cast<const float4*>(bias + tx*4);
    const int b  = m0 / SEQ;        // 64 | 4096, tile stays within one batch
    const int s0 = m0 % SEQ;
    #pragma unroll
    for (int i = 0; i < 4; ++i) {
        int s = s0 + ty*4 + i;
        float4 r;
        r.x = acc[i][0] + bias4.x;
        r.y = acc[i][1] + bias4.y;
        r.z = acc[i][2] + bias4.z;
        r.w = acc[i][3] + bias4.w;
        *reinterpret_cast<float4*>(&Out[((b*NHEADS + h)*SEQ + s)*DHEAD + tx*4]) = r;
    }
}

// ---------------------------------------------------------------------------
// Kernel 2: causal flash attention. One thread per query row, 128 rows/block.
// grid.x = SEQ/128, grid.y = B*H
// ---------------------------------------------------------------------------
__global__ __launch_bounds__(128) void flash_attn_kernel()
{
    __shared__ float Ksm[32][64];
    __shared__ float Vsm[32][64];

    const int tid = threadIdx.x;
    const int q0  = blockIdx.x * 128;
    const int bh  = blockIdx.y;                  // b*12 + h
    const int row = q0 + tid;

    const float* Qp = Qbuf + (bh*SEQ + row)*DHEAD;
    const float* Kp = Kbuf + bh*SEQ*DHEAD;
    const float* Vp = Vbuf + bh*SEQ*DHEAD;

    // Load q row, pre-scaled by 1/sqrt(64)
    float4 q4[16];
    #pragma unroll
    for (int t = 0; t < 16; ++t) {
        float4 v = reinterpret_cast<const float4*>(Qp)[t];
        q4[t].x = v.x * 0.125f; q4[t].y = v.y * 0.125f;
        q4[t].z = v.z * 0.125f; q4[t].w = v.w * 0.125f;
    }

    float4 o4[16];
    #pragma unroll
    for (int t = 0; t < 16; ++t) o4[t] = make_float4(0.f, 0.f, 0.f, 0.f);
    float m = -CUDART_INF_F;
    float l = 0.f;

    const int ntiles = q0/32 + 4;   // tiles with kt*32 <= q0+127

    for (int kt = 0; kt < ntiles; ++kt) {
        // Cooperative tile load: 32x64 each of K and V = 512 float4 each
        const float4* Ksrc = reinterpret_cast<const float4*>(Kp + kt*32*DHEAD);
        const float4* Vsrc = reinterpret_cast<const float4*>(Vp + kt*32*DHEAD);
        float4* Kd = reinterpret_cast<float4*>(&Ksm[0][0]);
        float4* Vd = reinterpret_cast<float4*>(&Vsm[0][0]);
        #pragma unroll
        for (int t = 0; t < 4; ++t) {
            Kd[t*128 + tid] = Ksrc[t*128 + tid];
            Vd[t*128 + tid] = Vsrc[t*128 + tid];
        }
        __syncthreads();

        if (kt*32 <= row) {
            float s[32];
            const float4* K4 = reinterpret_cast<const float4*>(&Ksm[0][0]);
            #pragma unroll
            for (int j = 0; j < 32; ++j) {
                float4 acc = make_float4(0.f, 0.f, 0.f, 0.f);
                const float4* kr = K4 + j*16;
                #pragma unroll
                for (int t = 0; t < 16; ++t) {
                    float4 kv = kr[t];
                    acc.x += q4[t].x * kv.x;
                    acc.y += q4[t].y * kv.y;
                    acc.z += q4[t].z * kv.z;
                    acc.w += q4[t].w * kv.w;
                }
                float d = (acc.x + acc.y) + (acc.z + acc.w);
                s[j] = (kt*32 + j <= row) ? d : -CUDART_INF_F;
            }

            // online softmax update
            float tmax = s[0];
            #pragma unroll
            for (int j = 1; j < 32; ++j) tmax = fmaxf(tmax, s[j]);
            float mnew = fmaxf(m, tmax);
            float corr = __expf(m - mnew);   // 0 if m == -inf (mnew finite since kt*32<=row)
            l *= corr;
            #pragma unroll
            for (int t = 0; t < 16; ++t) {
                o4[t].x *= corr; o4[t].y *= corr; o4[t].z *= corr; o4[t].w *= corr;
            }
            #pragma unroll
            for (int j = 0; j < 32; ++j) {
                float p = __expf(s[j] - mnew);
                s[j] = p;
                l += p;
            }
            const float4* V4 = reinterpret_cast<const float4*>(&Vsm[0][0]);
            #pragma unroll
            for (int j = 0; j < 32; ++j) {
                float p = s[j];
                const float4* vr = V4 + j*16;
                #pragma unroll
                for (int t = 0; t < 16; ++t) {
                    float4 vv = vr[t];
                    o4[t].x += p * vv.x;
                    o4[t].y += p * vv.y;
                    o4[t].z += p * vv.z;
                    o4[t].w += p * vv.w;
                }
            }
            m = mnew;
        }
        __syncthreads();
    }

    float inv = 1.f / l;
    float* Zp = Zbuf + (bh*SEQ + row)*DHEAD;
    #pragma unroll
    for (int t = 0; t < 16; ++t) {
        float4 r;
        r.x = o4[t].x * inv; r.y = o4[t].y * inv;
        r.z = o4[t].z * inv; r.w = o4[t].w * inv;
        reinterpret_cast<float4*>(Zp)[t] = r;
    }
}

// ---------------------------------------------------------------------------
// Kernel 3: output projection. Z [B,H,S,Z] viewed as [8192 x 768] (k = h*64+z)
// times W_O [768 x 768] row-major + b_O. grid.x = 128, grid.y = 12.
// ---------------------------------------------------------------------------
__global__ __launch_bounds__(256) void out_proj_kernel(
    const float* __restrict__ Wo, const float* __restrict__ bo,
    float* __restrict__ out)
{
    __shared__ float As[16][64];
    __shared__ float Bs[16][64];

    const int m0 = blockIdx.x * 64;
    const int n0 = blockIdx.y * 64;

    const int tid = threadIdx.x;
    const int tx  = tid % 16;
    const int ty  = tid / 16;
    const int arow = tid / 4,  akq = tid % 4;
    const int brow = tid / 16, bc4 = tid % 16;

    const int b  = m0 / SEQ;
    const int s0 = m0 % SEQ;

    float acc[4][4] = {};

    for (int k0 = 0; k0 < DMODEL; k0 += 16) {
        const int h  = k0 / DHEAD;        // constant within the 16-wide k tile
        const int z0 = k0 % DHEAD;
        float4 av = *reinterpret_cast<const float4*>(
            Zbuf + ((b*NHEADS + h)*SEQ + s0 + arow)*DHEAD + z0 + akq*4);
        As[akq*4+0][arow] = av.x;
        As[akq*4+1][arow] = av.y;
        As[akq*4+2][arow] = av.z;
        As[akq*4+3][arow] = av.w;
        *reinterpret_cast<float4*>(&Bs[brow][bc4*4]) =
            *reinterpret_cast<const float4*>(Wo + (k0 + brow) * DMODEL + n0 + bc4*4);
        __syncthreads();

        #pragma unroll
        for (int k = 0; k < 16; ++k) {
            float4 a = *reinterpret_cast<const float4*>(&As[k][ty*4]);
            float4 bb = *reinterpret_cast<const float4*>(&Bs[k][tx*4]);
            acc[0][0] += a.x*bb.x; acc[0][1] += a.x*bb.y; acc[0][2] += a.x*bb.z; acc[0][3] += a.x*bb.w;
            acc[1][0] += a.y*bb.x; acc[1][1] += a.y*bb.y; acc[1][2] += a.y*bb.z; acc[1][3] += a.y*bb.w;
            acc[2][0] += a.z*bb.x; acc[2][1] += a.z*bb.y; acc[2][2] += a.z*bb.z; acc[2][3] += a.z*bb.w;
            acc[3][0] += a.w*bb.x; acc[3][1] += a.w*bb.y; acc[3][2] += a.w*bb.z; acc[3][3] += a.w*bb.w;
        }
        __syncthreads();
    }

    float4 bias4 = *reinterpret_cast<const float4*>(bo + n0 + tx*4);
    #pragma unroll
    for (int i = 0; i < 4; ++i) {
        int mrow = m0 + ty*4 + i;
        float4 r;
        r.x = acc[i][0] + bias4.x;
        r.y = acc[i][1] + bias4.y;
        r.z = acc[i][2] + bias4.z;
        r.w = acc[i][3] + bias4.w;
        *reinterpret_cast<float4*>(&out[mrow * DMODEL + n0 + tx*4]) = r;
    }
}

// ---------------------------------------------------------------------------
extern "C" void kernel_launch(void* const* d_in, const int* in_sizes, int n_in,
                              void* d_out, int out_size)
{
    const float* x  = (const float*)d_in[0];
    const float* Wq = (const float*)d_in[1];
    const float* Wk = (const float*)d_in[2];
    const float* Wv = (const float*)d_in[3];
    const float* Wo = (const float*)d_in[4];
    const float* bq = (const float*)d_in[5];
    const float* bk = (const float*)d_in[6];
    const float* bv = (const float*)d_in[7];
    const float* bo = (const float*)d_in[8];
    float* out = (float*)d_out;

    dim3 g1(MTOT/64, 3*NHEADS);
    qkv_proj_kernel<<<g1, 256>>>(x, Wq, Wk, Wv, bq, bk, bv);

    dim3 g2(SEQ/128, BATCH*NHEADS);
    flash_attn_kernel<<<g2, 128>>>();

    dim3 g3(MTOT/64, DMODEL/64);
    out_proj_kernel<<<g3, 256>>>(Wo, bo, out);
}

// round 2
// speedup vs baseline: 2.2886x; 2.2886x over previous
#include <cuda_runtime.h>
#include <math_constants.h>
#include <cstdint>

// Problem dims
#define BATCH   2
#define SEQ     4096
#define DMODEL  768
#define NHEADS  12
#define DHEAD   64
#define MTOT    (BATCH*SEQ)          // 8192

// Intermediate buffers, layout [B, H, S, Z]
__device__ float Qbuf[BATCH*NHEADS*SEQ*DHEAD];
__device__ float Kbuf[BATCH*NHEADS*SEQ*DHEAD];
__device__ float Vbuf[BATCH*NHEADS*SEQ*DHEAD];
__device__ float Zbuf[BATCH*NHEADS*SEQ*DHEAD];

// ---------------------------------------------------------------------------
// tf32 mma helpers
// ---------------------------------------------------------------------------
__device__ __forceinline__ uint32_t f2tf32(float x) {
    uint32_t r;
    asm("cvt.rna.tf32.f32 %0, %1;" : "=r"(r) : "f"(x));
    return r;
}

__device__ __forceinline__ void mma_tf32(float c[4], const uint32_t a[4], const uint32_t b[2]) {
    asm volatile(
        "mma.sync.aligned.m16n8k8.row.col.f32.tf32.tf32.f32 "
        "{%0,%1,%2,%3}, {%4,%5,%6,%7}, {%8,%9}, {%0,%1,%2,%3};"
        : "+f"(c[0]), "+f"(c[1]), "+f"(c[2]), "+f"(c[3])
        : "r"(a[0]), "r"(a[1]), "r"(a[2]), "r"(a[3]), "r"(b[0]), "r"(b[1]));
}

// ---------------------------------------------------------------------------
// Kernel 1: fused QKV projection (fp32 FFMA, unchanged from round 0).
// ---------------------------------------------------------------------------
__global__ __launch_bounds__(256) void qkv_proj_kernel(
    const float* __restrict__ x,
    const float* __restrict__ Wq, const float* __restrict__ Wk, const float* __restrict__ Wv,
    const float* __restrict__ bq, const float* __restrict__ bk, const float* __restrict__ bv)
{
    __shared__ float As[16][64];   // [k][m]
    __shared__ float Bs[16][64];   // [k][n]

    const int m0  = blockIdx.x * 64;
    const int y   = blockIdx.y;
    const int mat = y / NHEADS;
    const int h   = y % NHEADS;

    const float* W    = (mat == 0 ? Wq : (mat == 1 ? Wk : Wv)) + h * DMODEL * DHEAD;
    const float* bias = (mat == 0 ? bq : (mat == 1 ? bk : bv)) + h * DHEAD;
    float* Out        = (mat == 0 ? Qbuf : (mat == 1 ? Kbuf : Vbuf));

    const int tid = threadIdx.x;
    const int tx  = tid % 16;
    const int ty  = tid / 16;
    const int arow = tid / 4,  akq = tid % 4;
    const int brow = tid / 16, bc4 = tid % 16;

    float acc[4][4] = {};

    for (int k0 = 0; k0 < DMODEL; k0 += 16) {
        float4 av = *reinterpret_cast<const float4*>(x + (m0 + arow) * DMODEL + k0 + akq * 4);
        As[akq*4+0][arow] = av.x;
        As[akq*4+1][arow] = av.y;
        As[akq*4+2][arow] = av.z;
        As[akq*4+3][arow] = av.w;
        *reinterpret_cast<float4*>(&Bs[brow][bc4*4]) =
            *reinterpret_cast<const float4*>(W + (k0 + brow) * DHEAD + bc4 * 4);
        __syncthreads();

        #pragma unroll
        for (int k = 0; k < 16; ++k) {
            float4 a = *reinterpret_cast<const float4*>(&As[k][ty*4]);
            float4 b = *reinterpret_cast<const float4*>(&Bs[k][tx*4]);
            acc[0][0] += a.x*b.x; acc[0][1] += a.x*b.y; acc[0][2] += a.x*b.z; acc[0][3] += a.x*b.w;
            acc[1][0] += a.y*b.x; acc[1][1] += a.y*b.y; acc[1][2] += a.y*b.z; acc[1][3] += a.y*b.w;
            acc[2][0] += a.z*b.x; acc[2][1] += a.z*b.y; acc[2][2] += a.z*b.z; acc[2][3] += a.z*b.w;
            acc[3][0] += a.w*b.x; acc[3][1] += a.w*b.y; acc[3][2] += a.w*b.z; acc[3][3] += a.w*b.w;
        }
        __syncthreads();
    }

    float4 bias4 = *reinterpret_cast<const float4*>(bias + tx*4);
    const int b  = m0 / SEQ;
    const int s0 = m0 % SEQ;
    #pragma unroll
    for (int i = 0; i < 4; ++i) {
        int s = s0 + ty*4 + i;
        float4 r;
        r.x = acc[i][0] + bias4.x;
        r.y = acc[i][1] + bias4.y;
        r.z = acc[i][2] + bias4.z;
        r.w = acc[i][3] + bias4.w;
        *reinterpret_cast<float4*>(&Out[((b*NHEADS + h)*SEQ + s)*DHEAD + tx*4]) = r;
    }
}

// ---------------------------------------------------------------------------
// Kernel 2: causal flash attention with tf32 tensor cores.
// Block = 128 threads (4 warps). Each block: 64 query rows. K/V tiles = 32 keys.
// grid = (SEQ/64, B*H)
// ---------------------------------------------------------------------------
#define TQ 64
#define TK 32
#define KSTR 68   // Ksm/Vsm row stride (floats): bank = 4r+c pattern, conflict-free frags
#define PSTR 36   // Psm row stride

__global__ __launch_bounds__(128) void flash_attn_mma()
{
    __shared__ float Ksm[TK][KSTR];
    __shared__ float Vsm[TK][KSTR];
    __shared__ float Psm[TQ][PSTR];

    const int tid  = threadIdx.x;
    const int w    = tid >> 5;
    const int lane = tid & 31;
    const int rA   = lane >> 2;   // 0..7
    const int cA   = lane & 3;    // 0..3
    const int q0   = blockIdx.x * TQ;
    const int bh   = blockIdx.y;

    const float* Qg = Qbuf + (size_t)(bh*SEQ + q0 + w*16) * DHEAD;
    const float* Kg = Kbuf + (size_t)bh * SEQ * DHEAD;
    const float* Vg = Vbuf + (size_t)bh * SEQ * DHEAD;

    // Q fragments for this warp's 16 rows, whole head dim (8 k-steps), prescaled
    uint32_t qf[8][4];
    #pragma unroll
    for (int ks = 0; ks < 8; ++ks) {
        qf[ks][0] = f2tf32(Qg[(rA    )*DHEAD + ks*8 + cA    ] * 0.125f);
        qf[ks][1] = f2tf32(Qg[(rA + 8)*DHEAD + ks*8 + cA    ] * 0.125f);
        qf[ks][2] = f2tf32(Qg[(rA    )*DHEAD + ks*8 + cA + 4] * 0.125f);
        qf[ks][3] = f2tf32(Qg[(rA + 8)*DHEAD + ks*8 + cA + 4] * 0.125f);
    }

    float o[8][4];
    #pragma unroll
    for (int jt = 0; jt < 8; ++jt) { o[jt][0]=0.f; o[jt][1]=0.f; o[jt][2]=0.f; o[jt][3]=0.f; }
    float m0 = -CUDART_INF_F, m1 = -CUDART_INF_F;
    float l0 = 0.f, l1 = 0.f;

    const int ntiles = q0/TK + 2;   // keys up to q0+63

    for (int kt = 0; kt < ntiles; ++kt) {
        __syncthreads();
        // Cooperative K/V tile load: 32x64 floats each, cvt to tf32 on the way in
        #pragma unroll
        for (int i = 0; i < 4; ++i) {
            int e   = tid + i*128;     // float4 index 0..511
            int row = e >> 4, c4 = e & 15;
            float4 kv = *reinterpret_cast<const float4*>(Kg + (size_t)(kt*TK + row)*DHEAD + c4*4);
            float4 vv = *reinterpret_cast<const float4*>(Vg + (size_t)(kt*TK + row)*DHEAD + c4*4);
            Ksm[row][c4*4+0] = __uint_as_float(f2tf32(kv.x));
            Ksm[row][c4*4+1] = __uint_as_float(f2tf32(kv.y));
            Ksm[row][c4*4+2] = __uint_as_float(f2tf32(kv.z));
            Ksm[row][c4*4+3] = __uint_as_float(f2tf32(kv.w));
            Vsm[row][c4*4+0] = __uint_as_float(f2tf32(vv.x));
            Vsm[row][c4*4+1] = __uint_as_float(f2tf32(vv.y));
            Vsm[row][c4*4+2] = __uint_as_float(f2tf32(vv.z));
            Vsm[row][c4*4+3] = __uint_as_float(f2tf32(vv.w));
        }
        __syncthreads();

        // S = Q @ K^T for this warp: 16 x 32 scores in 4 n-tiles
        float sc[4][4] = {};
        #pragma unroll
        for (int ks = 0; ks < 8; ++ks) {
            #pragma unroll
            for (int jt = 0; jt < 4; ++jt) {
                uint32_t b[2];
                b[0] = __float_as_uint(Ksm[jt*8 + rA][ks*8 + cA    ]);
                b[1] = __float_as_uint(Ksm[jt*8 + rA][ks*8 + cA + 4]);
                mma_tf32(sc[jt], qf[ks], b);
            }
        }

        // Causal mask (only the last two tiles can overlap the diagonal)
        if (kt >= ntiles - 2) {
            const int r0g = q0 + w*16 + rA;
            #pragma unroll
            for (int jt = 0; jt < 4; ++jt) {
                int key = kt*TK + jt*8 + 2*cA;
                if (key     > r0g    ) sc[jt][0] = -CUDART_INF_F;
                if (key + 1 > r0g    ) sc[jt][1] = -CUDART_INF_F;
                if (key     > r0g + 8) sc[jt][2] = -CUDART_INF_F;
                if (key + 1 > r0g + 8) sc[jt][3] = -CUDART_INF_F;
            }
        }

        // Online softmax (rows rA and rA+8). Row spread across 4 lanes of a quad.
        float rmax0 = fmaxf(fmaxf(sc[0][0], sc[0][1]), fmaxf(sc[1][0], sc[1][1]));
        rmax0 = fmaxf(rmax0, fmaxf(fmaxf(sc[2][0], sc[2][1]), fmaxf(sc[3][0], sc[3][1])));
        float rmax1 = fmaxf(fmaxf(sc[0][2], sc[0][3]), fmaxf(sc[1][2], sc[1][3]));
        rmax1 = fmaxf(rmax1, fmaxf(fmaxf(sc[2][2], sc[2][3]), fmaxf(sc[3][2], sc[3][3])));
        rmax0 = fmaxf(rmax0, __shfl_xor_sync(0xffffffffu, rmax0, 1));
        rmax0 = fmaxf(rmax0, __shfl_xor_sync(0xffffffffu, rmax0, 2));
        rmax1 = fmaxf(rmax1, __shfl_xor_sync(0xffffffffu, rmax1, 1));
        rmax1 = fmaxf(rmax1, __shfl_xor_sync(0xffffffffu, rmax1, 2));

        float mn0 = fmaxf(m0, rmax0);
        float mn1 = fmaxf(m1, rmax1);
        float f0 = __expf(m0 - mn0);   // 0 when m0 == -inf
        float f1 = __expf(m1 - mn1);
        l0 *= f0; l1 *= f1;
        #pragma unroll
        for (int jt = 0; jt < 8; ++jt) {
            o[jt][0] *= f0; o[jt][1] *= f0;
            o[jt][2] *= f1; o[jt][3] *= f1;
        }

        #pragma unroll
        for (int jt = 0; jt < 4; ++jt) {
            float p0 = __expf(sc[jt][0] - mn0);
            float p1 = __expf(sc[jt][1] - mn0);
            float p2 = __expf(sc[jt][2] - mn1);
            float p3 = __expf(sc[jt][3] - mn1);
            l0 += p0 + p1;
            l1 += p2 + p3;
            int col = jt*8 + 2*cA;
            float2 lo = make_float2(__uint_as_float(f2tf32(p0)), __uint_as_float(f2tf32(p1)));
            float2 hi = make_float2(__uint_as_float(f2tf32(p2)), __uint_as_float(f2tf32(p3)));
            *reinterpret_cast<float2*>(&Psm[w*16 + rA    ][col]) = lo;
            *reinterpret_cast<float2*>(&Psm[w*16 + rA + 8][col]) = hi;
        }
        m0 = mn0; m1 = mn1;
        __syncwarp();

        // O += P @ V   (P: 16x32, V: 32x64)
        #pragma unroll
        for (int kq = 0; kq < 4; ++kq) {
            uint32_t a[4];
            a[0] = __float_as_uint(Psm[w*16 + rA    ][kq*8 + cA    ]);
            a[1] = __float_as_uint(Psm[w*16 + rA + 8][kq*8 + cA    ]);
            a[2] = __float_as_uint(Psm[w*16 + rA    ][kq*8 + cA + 4]);
            a[3] = __float_as_uint(Psm[w*16 + rA + 8][kq*8 + cA + 4]);
            #pragma unroll
            for (int jt = 0; jt < 8; ++jt) {
                uint32_t b[2];
                b[0] = __float_as_uint(Vsm[kq*8 + cA    ][jt*8 + rA]);
                b[1] = __float_as_uint(Vsm[kq*8 + cA + 4][jt*8 + rA]);
                mma_tf32(o[jt], a, b);
            }
        }
    }

    // Final row-sum reduction across quad + normalize + store
    l0 += __shfl_xor_sync(0xffffffffu, l0, 1);
    l0 += __shfl_xor_sync(0xffffffffu, l0, 2);
    l1 += __shfl_xor_sync(0xffffffffu, l1, 1);
    l1 += __shfl_xor_sync(0xffffffffu, l1, 2);
    float inv0 = 1.f / l0;
    float inv1 = 1.f / l1;

    float* Zp = Zbuf + (size_t)(bh*SEQ + q0 + w*16) * DHEAD;
    #pragma unroll
    for (int jt = 0; jt < 8; ++jt) {
        int col = jt*8 + 2*cA;
        *reinterpret_cast<float2*>(&Zp[(rA    )*DHEAD + col]) =
            make_float2(o[jt][0]*inv0, o[jt][1]*inv0);
        *reinterpret_cast<float2*>(&Zp[(rA + 8)*DHEAD + col]) =
            make_float2(o[jt][2]*inv1, o[jt][3]*inv1);
    }
}

// ---------------------------------------------------------------------------
// Kernel 3: output projection (fp32 FFMA, unchanged from round 0).
// ---------------------------------------------------------------------------
__global__ __launch_bounds__(256) void out_proj_kernel(
    const float* __restrict__ Wo, const float* __restrict__ bo,
    float* __restrict__ out)
{
    __shared__ float As[16][64];
    __shared__ float Bs[16][64];

    const int m0 = blockIdx.x * 64;
    const int n0 = blockIdx.y * 64;

    const int tid = threadIdx.x;
    const int tx  = tid % 16;
    const int ty  = tid / 16;
    const int arow = tid / 4,  akq = tid % 4;
    const int brow = tid / 16, bc4 = tid % 16;

    const int b  = m0 / SEQ;
    const int s0 = m0 % SEQ;

    float acc[4][4] = {};

    for (int k0 = 0; k0 < DMODEL; k0 += 16) {
        const int h  = k0 / DHEAD;
        const int z0 = k0 % DHEAD;
        float4 av = *reinterpret_cast<const float4*>(
            Zbuf + ((b*NHEADS + h)*SEQ + s0 + arow)*DHEAD + z0 + akq*4);
        As[akq*4+0][arow] = av.x;
        As[akq*4+1][arow] = av.y;
        As[akq*4+2][arow] = av.z;
        As[akq*4+3][arow] = av.w;
        *reinterpret_cast<float4*>(&Bs[brow][bc4*4]) =
            *reinterpret_cast<const float4*>(Wo + (k0 + brow) * DMODEL + n0 + bc4*4);
        __syncthreads();

        #pragma unroll
        for (int k = 0; k < 16; ++k) {
            float4 a = *reinterpret_cast<const float4*>(&As[k][ty*4]);
            float4 bb = *reinterpret_cast<const float4*>(&Bs[k][tx*4]);
            acc[0][0] += a.x*bb.x; acc[0][1] += a.x*bb.y; acc[0][2] += a.x*bb.z; acc[0][3] += a.x*bb.w;
            acc[1][0] += a.y*bb.x; acc[1][1] += a.y*bb.y; acc[1][2] += a.y*bb.z; acc[1][3] += a.y*bb.w;
            acc[2][0] += a.z*bb.x; acc[2][1] += a.z*bb.y; acc[2][2] += a.z*bb.z; acc[2][3] += a.z*bb.w;
            acc[3][0] += a.w*bb.x; acc[3][1] += a.w*bb.y; acc[3][2] += a.w*bb.z; acc[3][3] += a.w*bb.w;
        }
        __syncthreads();
    }

    float4 bias4 = *reinterpret_cast<const float4*>(bo + n0 + tx*4);
    #pragma unroll
    for (int i = 0; i < 4; ++i) {
        int mrow = m0 + ty*4 + i;
        float4 r;
        r.x = acc[i][0] + bias4.x;
        r.y = acc[i][1] + bias4.y;
        r.z = acc[i][2] + bias4.z;
        r.w = acc[i][3] + bias4.w;
        *reinterpret_cast<float4*>(&out[mrow * DMODEL + n0 + tx*4]) = r;
    }
}

// ---------------------------------------------------------------------------
extern "C" void kernel_launch(void* const* d_in, const int* in_sizes, int n_in,
                              void* d_out, int out_size)
{
    const float* x  = (const float*)d_in[0];
    const float* Wq = (const float*)d_in[1];
    const float* Wk = (const float*)d_in[2];
    const float* Wv = (const float*)d_in[3];
    const float* Wo = (const float*)d_in[4];
    const float* bq = (const float*)d_in[5];
    const float* bk = (const float*)d_in[6];
    const float* bv = (const float*)d_in[7];
    const float* bo = (const float*)d_in[8];
    float* out = (float*)d_out;

    dim3 g1(MTOT/64, 3*NHEADS);
    qkv_proj_kernel<<<g1, 256>>>(x, Wq, Wk, Wv, bq, bk, bv);

    dim3 g2(SEQ/TQ, BATCH*NHEADS);
    flash_attn_mma<<<g2, 128>>>();

    dim3 g3(MTOT/64, DMODEL/64);
    out_proj_kernel<<<g3, 256>>>(Wo, bo, out);
}

// round 3
// speedup vs baseline: 3.8580x; 1.6858x over previous
#include <cuda_runtime.h>
#include <math_constants.h>
#include <cstdint>

// Problem dims
#define BATCH   2
#define SEQ     4096
#define DMODEL  768
#define NHEADS  12
#define DHEAD   64
#define MTOT    (BATCH*SEQ)          // 8192

// Intermediate buffers, layout [B, H, S, Z]
__device__ float Qbuf[BATCH*NHEADS*SEQ*DHEAD];
__device__ float Kbuf[BATCH*NHEADS*SEQ*DHEAD];
__device__ float Vbuf[BATCH*NHEADS*SEQ*DHEAD];
__device__ float Zbuf[BATCH*NHEADS*SEQ*DHEAD];

// ---------------------------------------------------------------------------
// tf32 mma helpers
// ---------------------------------------------------------------------------
__device__ __forceinline__ uint32_t f2tf32(float x) {
    uint32_t r;
    asm("cvt.rna.tf32.f32 %0, %1;" : "=r"(r) : "f"(x));
    return r;
}

__device__ __forceinline__ void mma_tf32(float c[4], const uint32_t a[4], const uint32_t b[2]) {
    asm volatile(
        "mma.sync.aligned.m16n8k8.row.col.f32.tf32.tf32.f32 "
        "{%0,%1,%2,%3}, {%4,%5,%6,%7}, {%8,%9}, {%0,%1,%2,%3};"
        : "+f"(c[0]), "+f"(c[1]), "+f"(c[2]), "+f"(c[3])
        : "r"(a[0]), "r"(a[1]), "r"(a[2]), "r"(a[3]), "r"(b[0]), "r"(b[1]));
}

// ---------------------------------------------------------------------------
// Kernel 1: fused QKV projection, tf32 tensor cores.
// Block 256 thr (8 warps), tile 128(M) x 64(N), K-chunk 32.
// grid = (MTOT/128, 36): y -> (mat in {Q,K,V}, head)
// ---------------------------------------------------------------------------
#define GAPAD 36
#define GBPAD 68

__global__ __launch_bounds__(256) void qkv_proj_tf32(
    const float* __restrict__ x,
    const float* __restrict__ Wq, const float* __restrict__ Wk, const float* __restrict__ Wv,
    const float* __restrict__ bq, const float* __restrict__ bk, const float* __restrict__ bv)
{
    __shared__ float As[128][GAPAD];   // [m][k], tf32 bits
    __shared__ float Bs[32][GBPAD];    // [k][n], tf32 bits

    const int m0  = blockIdx.x * 128;
    const int y   = blockIdx.y;
    const int mat = y / NHEADS;
    const int h   = y % NHEADS;

    const float* W    = (mat == 0 ? Wq : (mat == 1 ? Wk : Wv)) + h * DMODEL * DHEAD;
    const float* bias = (mat == 0 ? bq : (mat == 1 ? bk : bv)) + h * DHEAD;
    float* Out        = (mat == 0 ? Qbuf : (mat == 1 ? Kbuf : Vbuf));

    const int tid  = threadIdx.x;
    const int w    = tid >> 5;
    const int lane = tid & 31;
    const int rA   = lane >> 2;
    const int cA   = lane & 3;
    const int moff = (w & 3) * 32;
    const int noff = (w >> 2) * 32;

    float acc[2][4][4] = {};

    for (int k0 = 0; k0 < DMODEL; k0 += 32) {
        // A tile: 128 x 32 = 1024 float4, 4 per thread
        #pragma unroll
        for (int i = 0; i < 4; ++i) {
            int e = tid + i * 256;
            int row = e >> 3, c4 = e & 7;
            float4 v = *reinterpret_cast<const float4*>(x + (size_t)(m0 + row) * DMODEL + k0 + c4 * 4);
            As[row][c4*4+0] = __uint_as_float(f2tf32(v.x));
            As[row][c4*4+1] = __uint_as_float(f2tf32(v.y));
            As[row][c4*4+2] = __uint_as_float(f2tf32(v.z));
            As[row][c4*4+3] = __uint_as_float(f2tf32(v.w));
        }
        // B tile: 32 x 64 = 512 float4, 2 per thread
        #pragma unroll
        for (int i = 0; i < 2; ++i) {
            int e = tid + i * 256;
            int row = e >> 4, c4 = e & 15;
            float4 v = *reinterpret_cast<const float4*>(W + (size_t)(k0 + row) * DHEAD + c4 * 4);
            Bs[row][c4*4+0] = __uint_as_float(f2tf32(v.x));
            Bs[row][c4*4+1] = __uint_as_float(f2tf32(v.y));
            Bs[row][c4*4+2] = __uint_as_float(f2tf32(v.z));
            Bs[row][c4*4+3] = __uint_as_float(f2tf32(v.w));
        }
        __syncthreads();

        #pragma unroll
        for (int kk = 0; kk < 4; ++kk) {
            const int kb = kk * 8;
            uint32_t a[2][4];
            #pragma unroll
            for (int f = 0; f < 2; ++f) {
                a[f][0] = __float_as_uint(As[moff + f*16 + rA    ][kb + cA    ]);
                a[f][1] = __float_as_uint(As[moff + f*16 + rA + 8][kb + cA    ]);
                a[f][2] = __float_as_uint(As[moff + f*16 + rA    ][kb + cA + 4]);
                a[f][3] = __float_as_uint(As[moff + f*16 + rA + 8][kb + cA + 4]);
            }
            uint32_t b[4][2];
            #pragma unroll
            for (int j = 0; j < 4; ++j) {
                b[j][0] = __float_as_uint(Bs[kb + cA    ][noff + j*8 + rA]);
                b[j][1] = __float_as_uint(Bs[kb + cA + 4][noff + j*8 + rA]);
            }
            #pragma unroll
            for (int f = 0; f < 2; ++f)
                #pragma unroll
                for (int j = 0; j < 4; ++j)
                    mma_tf32(acc[f][j], a[f], b[j]);
        }
        __syncthreads();
    }

    // Epilogue: bias + store to [B,H,S,Z]
    const int b  = m0 / SEQ;
    const int s0 = m0 % SEQ;
    #pragma unroll
    for (int f = 0; f < 2; ++f) {
        #pragma unroll
        for (int j = 0; j < 4; ++j) {
            int col = noff + j*8 + 2*cA;
            float b0 = bias[col], b1 = bias[col + 1];
            int s = s0 + moff + f*16 + rA;
            *reinterpret_cast<float2*>(&Out[((size_t)(b*NHEADS + h)*SEQ + s)*DHEAD + col]) =
                make_float2(acc[f][j][0] + b0, acc[f][j][1] + b1);
            *reinterpret_cast<float2*>(&Out[((size_t)(b*NHEADS + h)*SEQ + s + 8)*DHEAD + col]) =
                make_float2(acc[f][j][2] + b0, acc[f][j][3] + b1);
        }
    }
}

// ---------------------------------------------------------------------------
// Kernel 2: causal flash attention with tf32 tensor cores (unchanged R1).
// ---------------------------------------------------------------------------
#define TQ 64
#define TK 32
#define KSTR 68
#define PSTR 36

__global__ __launch_bounds__(128) void flash_attn_mma()
{
    __shared__ float Ksm[TK][KSTR];
    __shared__ float Vsm[TK][KSTR];
    __shared__ float Psm[TQ][PSTR];

    const int tid  = threadIdx.x;
    const int w    = tid >> 5;
    const int lane = tid & 31;
    const int rA   = lane >> 2;
    const int cA   = lane & 3;
    const int q0   = blockIdx.x * TQ;
    const int bh   = blockIdx.y;

    const float* Qg = Qbuf + (size_t)(bh*SEQ + q0 + w*16) * DHEAD;
    const float* Kg = Kbuf + (size_t)bh * SEQ * DHEAD;
    const float* Vg = Vbuf + (size_t)bh * SEQ * DHEAD;

    uint32_t qf[8][4];
    #pragma unroll
    for (int ks = 0; ks < 8; ++ks) {
        qf[ks][0] = f2tf32(Qg[(rA    )*DHEAD + ks*8 + cA    ] * 0.125f);
        qf[ks][1] = f2tf32(Qg[(rA + 8)*DHEAD + ks*8 + cA    ] * 0.125f);
        qf[ks][2] = f2tf32(Qg[(rA    )*DHEAD + ks*8 + cA + 4] * 0.125f);
        qf[ks][3] = f2tf32(Qg[(rA + 8)*DHEAD + ks*8 + cA + 4] * 0.125f);
    }

    float o[8][4];
    #pragma unroll
    for (int jt = 0; jt < 8; ++jt) { o[jt][0]=0.f; o[jt][1]=0.f; o[jt][2]=0.f; o[jt][3]=0.f; }
    float m0 = -CUDART_INF_F, m1 = -CUDART_INF_F;
    float l0 = 0.f, l1 = 0.f;

    const int ntiles = q0/TK + 2;

    for (int kt = 0; kt < ntiles; ++kt) {
        __syncthreads();
        #pragma unroll
        for (int i = 0; i < 4; ++i) {
            int e   = tid + i*128;
            int row = e >> 4, c4 = e & 15;
            float4 kv = *reinterpret_cast<const float4*>(Kg + (size_t)(kt*TK + row)*DHEAD + c4*4);
            float4 vv = *reinterpret_cast<const float4*>(Vg + (size_t)(kt*TK + row)*DHEAD + c4*4);
            Ksm[row][c4*4+0] = __uint_as_float(f2tf32(kv.x));
            Ksm[row][c4*4+1] = __uint_as_float(f2tf32(kv.y));
            Ksm[row][c4*4+2] = __uint_as_float(f2tf32(kv.z));
            Ksm[row][c4*4+3] = __uint_as_float(f2tf32(kv.w));
            Vsm[row][c4*4+0] = __uint_as_float(f2tf32(vv.x));
            Vsm[row][c4*4+1] = __uint_as_float(f2tf32(vv.y));
            Vsm[row][c4*4+2] = __uint_as_float(f2tf32(vv.z));
            Vsm[row][c4*4+3] = __uint_as_float(f2tf32(vv.w));
        }
        __syncthreads();

        float sc[4][4] = {};
        #pragma unroll
        for (int ks = 0; ks < 8; ++ks) {
            #pragma unroll
            for (int jt = 0; jt < 4; ++jt) {
                uint32_t b[2];
                b[0] = __float_as_uint(Ksm[jt*8 + rA][ks*8 + cA    ]);
                b[1] = __float_as_uint(Ksm[jt*8 + rA][ks*8 + cA + 4]);
                mma_tf32(sc[jt], qf[ks], b);
            }
        }

        if (kt >= ntiles - 2) {
            const int r0g = q0 + w*16 + rA;
            #pragma unroll
            for (int jt = 0; jt < 4; ++jt) {
                int key = kt*TK + jt*8 + 2*cA;
                if (key     > r0g    ) sc[jt][0] = -CUDART_INF_F;
                if (key + 1 > r0g    ) sc[jt][1] = -CUDART_INF_F;
                if (key     > r0g + 8) sc[jt][2] = -CUDART_INF_F;
                if (key + 1 > r0g + 8) sc[jt][3] = -CUDART_INF_F;
            }
        }

        float rmax0 = fmaxf(fmaxf(sc[0][0], sc[0][1]), fmaxf(sc[1][0], sc[1][1]));
        rmax0 = fmaxf(rmax0, fmaxf(fmaxf(sc[2][0], sc[2][1]), fmaxf(sc[3][0], sc[3][1])));
        float rmax1 = fmaxf(fmaxf(sc[0][2], sc[0][3]), fmaxf(sc[1][2], sc[1][3]));
        rmax1 = fmaxf(rmax1, fmaxf(fmaxf(sc[2][2], sc[2][3]), fmaxf(sc[3][2], sc[3][3])));
        rmax0 = fmaxf(rmax0, __shfl_xor_sync(0xffffffffu, rmax0, 1));
        rmax0 = fmaxf(rmax0, __shfl_xor_sync(0xffffffffu, rmax0, 2));
        rmax1 = fmaxf(rmax1, __shfl_xor_sync(0xffffffffu, rmax1, 1));
        rmax1 = fmaxf(rmax1, __shfl_xor_sync(0xffffffffu, rmax1, 2));

        float mn0 = fmaxf(m0, rmax0);
        float mn1 = fmaxf(m1, rmax1);
        float f0 = __expf(m0 - mn0);
        float f1 = __expf(m1 - mn1);
        l0 *= f0; l1 *= f1;
        #pragma unroll
        for (int jt = 0; jt < 8; ++jt) {
            o[jt][0] *= f0; o[jt][1] *= f0;
            o[jt][2] *= f1; o[jt][3] *= f1;
        }

        #pragma unroll
        for (int jt = 0; jt < 4; ++jt) {
            float p0 = __expf(sc[jt][0] - mn0);
            float p1 = __expf(sc[jt][1] - mn0);
            float p2 = __expf(sc[jt][2] - mn1);
            float p3 = __expf(sc[jt][3] - mn1);
            l0 += p0 + p1;
            l1 += p2 + p3;
            int col = jt*8 + 2*cA;
            float2 lo = make_float2(__uint_as_float(f2tf32(p0)), __uint_as_float(f2tf32(p1)));
            float2 hi = make_float2(__uint_as_float(f2tf32(p2)), __uint_as_float(f2tf32(p3)));
            *reinterpret_cast<float2*>(&Psm[w*16 + rA    ][col]) = lo;
            *reinterpret_cast<float2*>(&Psm[w*16 + rA + 8][col]) = hi;
        }
        m0 = mn0; m1 = mn1;
        __syncwarp();

        #pragma unroll
        for (int kq = 0; kq < 4; ++kq) {
            uint32_t a[4];
            a[0] = __float_as_uint(Psm[w*16 + rA    ][kq*8 + cA    ]);
            a[1] = __float_as_uint(Psm[w*16 + rA + 8][kq*8 + cA    ]);
            a[2] = __float_as_uint(Psm[w*16 + rA    ][kq*8 + cA + 4]);
            a[3] = __float_as_uint(Psm[w*16 + rA + 8][kq*8 + cA + 4]);
            #pragma unroll
            for (int jt = 0; jt < 8; ++jt) {
                uint32_t b[2];
                b[0] = __float_as_uint(Vsm[kq*8 + cA    ][jt*8 + rA]);
                b[1] = __float_as_uint(Vsm[kq*8 + cA + 4][jt*8 + rA]);
                mma_tf32(o[jt], a, b);
            }
        }
    }

    l0 += __shfl_xor_sync(0xffffffffu, l0, 1);
    l0 += __shfl_xor_sync(0xffffffffu, l0, 2);
    l1 += __shfl_xor_sync(0xffffffffu, l1, 1);
    l1 += __shfl_xor_sync(0xffffffffu, l1, 2);
    float inv0 = 1.f / l0;
    float inv1 = 1.f / l1;

    float* Zp = Zbuf + (size_t)(bh*SEQ + q0 + w*16) * DHEAD;
    #pragma unroll
    for (int jt = 0; jt < 8; ++jt) {
        int col = jt*8 + 2*cA;
        *reinterpret_cast<float2*>(&Zp[(rA    )*DHEAD + col]) =
            make_float2(o[jt][0]*inv0, o[jt][1]*inv0);
        *reinterpret_cast<float2*>(&Zp[(rA + 8)*DHEAD + col]) =
            make_float2(o[jt][2]*inv1, o[jt][3]*inv1);
    }
}

// ---------------------------------------------------------------------------
// Kernel 3: output projection, tf32 tensor cores.
// Block 256 thr, tile 128(M) x 64(N), K-chunk 32 (stays within one head).
// grid = (MTOT/128, DMODEL/64)
// ---------------------------------------------------------------------------
__global__ __launch_bounds__(256) void out_proj_tf32(
    const float* __restrict__ Wo, const float* __restrict__ bo,
    float* __restrict__ out)
{
    __shared__ float As[128][GAPAD];
    __shared__ float Bs[32][GBPAD];

    const int m0 = blockIdx.x * 128;
    const int n0 = blockIdx.y * 64;

    const int tid  = threadIdx.x;
    const int w    = tid >> 5;
    const int lane = tid & 31;
    const int rA   = lane >> 2;
    const int cA   = lane & 3;
    const int moff = (w & 3) * 32;
    const int noff = (w >> 2) * 32;

    const int bb = m0 / SEQ;
    const int s0 = m0 % SEQ;

    float acc[2][4][4] = {};

    for (int k0 = 0; k0 < DMODEL; k0 += 32) {
        const int h  = k0 / DHEAD;
        const int z0 = k0 % DHEAD;
        const float* Zp = Zbuf + ((size_t)(bb*NHEADS + h)*SEQ + s0)*DHEAD + z0;
        #pragma unroll
        for (int i = 0; i < 4; ++i) {
            int e = tid + i * 256;
            int row = e >> 3, c4 = e & 7;
            float4 v = *reinterpret_cast<const float4*>(Zp + (size_t)row * DHEAD + c4 * 4);
            As[row][c4*4+0] = __uint_as_float(f2tf32(v.x));
            As[row][c4*4+1] = __uint_as_float(f2tf32(v.y));
            As[row][c4*4+2] = __uint_as_float(f2tf32(v.z));
            As[row][c4*4+3] = __uint_as_float(f2tf32(v.w));
        }
        #pragma unroll
        for (int i = 0; i < 2; ++i) {
            int e = tid + i * 256;
            int row = e >> 4, c4 = e & 15;
            float4 v = *reinterpret_cast<const float4*>(Wo + (size_t)(k0 + row) * DMODEL + n0 + c4 * 4);
            Bs[row][c4*4+0] = __uint_as_float(f2tf32(v.x));
            Bs[row][c4*4+1] = __uint_as_float(f2tf32(v.y));
            Bs[row][c4*4+2] = __uint_as_float(f2tf32(v.z));
            Bs[row][c4*4+3] = __uint_as_float(f2tf32(v.w));
        }
        __syncthreads();

        #pragma unroll
        for (int kk = 0; kk < 4; ++kk) {
            const int kb = kk * 8;
            uint32_t a[2][4];
            #pragma unroll
            for (int f = 0; f < 2; ++f) {
                a[f][0] = __float_as_uint(As[moff + f*16 + rA    ][kb + cA    ]);
                a[f][1] = __float_as_uint(As[moff + f*16 + rA + 8][kb + cA    ]);
                a[f][2] = __float_as_uint(As[moff + f*16 + rA    ][kb + cA + 4]);
                a[f][3] = __float_as_uint(As[moff + f*16 + rA + 8][kb + cA + 4]);
            }
            uint32_t b[4][2];
            #pragma unroll
            for (int j = 0; j < 4; ++j) {
                b[j][0] = __float_as_uint(Bs[kb + cA    ][noff + j*8 + rA]);
                b[j][1] = __float_as_uint(Bs[kb + cA + 4][noff + j*8 + rA]);
            }
            #pragma unroll
            for (int f = 0; f < 2; ++f)
                #pragma unroll
                for (int j = 0; j < 4; ++j)
                    mma_tf32(acc[f][j], a[f], b[j]);
        }
        __syncthreads();
    }

    #pragma unroll
    for (int f = 0; f < 2; ++f) {
        #pragma unroll
        for (int j = 0; j < 4; ++j) {
            int col = n0 + noff + j*8 + 2*cA;
            float b0 = bo[col], b1 = bo[col + 1];
            int mrow = m0 + moff + f*16 + rA;
            *reinterpret_cast<float2*>(&out[(size_t)mrow * DMODEL + col]) =
                make_float2(acc[f][j][0] + b0, acc[f][j][1] + b1);
            *reinterpret_cast<float2*>(&out[(size_t)(mrow + 8) * DMODEL + col]) =
                make_float2(acc[f][j][2] + b0, acc[f][j][3] + b1);
        }
    }
}

// ---------------------------------------------------------------------------
extern "C" void kernel_launch(void* const* d_in, const int* in_sizes, int n_in,
                              void* d_out, int out_size)
{
    const float* x  = (const float*)d_in[0];
    const float* Wq = (const float*)d_in[1];
    const float* Wk = (const float*)d_in[2];
    const float* Wv = (const float*)d_in[3];
    const float* Wo = (const float*)d_in[4];
    const float* bq = (const float*)d_in[5];
    const float* bk = (const float*)d_in[6];
    const float* bv = (const float*)d_in[7];
    const float* bo = (const float*)d_in[8];
    float* out = (float*)d_out;

    dim3 g1(MTOT/128, 3*NHEADS);
    qkv_proj_tf32<<<g1, 256>>>(x, Wq, Wk, Wv, bq, bk, bv);

    dim3 g2(SEQ/TQ, BATCH*NHEADS);
    flash_attn_mma<<<g2, 128>>>();

    dim3 g3(MTOT/128, DMODEL/64);
    out_proj_tf32<<<g3, 256>>>(Wo, bo, out);
}

// round 5
// speedup vs baseline: 3.8955x; 1.0097x over previous
#include <cuda_runtime.h>
#include <math_constants.h>
#include <cstdint>

// Problem dims
#define BATCH   2
#define SEQ     4096
#define DMODEL  768
#define NHEADS  12
#define DHEAD   64
#define MTOT    (BATCH*SEQ)          // 8192

// Intermediate buffers, layout [B, H, S, Z]
__device__ float Qbuf[BATCH*NHEADS*SEQ*DHEAD];
__device__ float Kbuf[BATCH*NHEADS*SEQ*DHEAD];
__device__ float Vbuf[BATCH*NHEADS*SEQ*DHEAD];
__device__ float Zbuf[BATCH*NHEADS*SEQ*DHEAD];

// ---------------------------------------------------------------------------
// helpers
// ---------------------------------------------------------------------------
__device__ __forceinline__ uint32_t f2tf32(float x) {
    uint32_t r;
    asm("cvt.rna.tf32.f32 %0, %1;" : "=r"(r) : "f"(x));
    return r;
}

__device__ __forceinline__ void mma_tf32(float c[4], const uint32_t a[4], const uint32_t b[2]) {
    asm volatile(
        "mma.sync.aligned.m16n8k8.row.col.f32.tf32.tf32.f32 "
        "{%0,%1,%2,%3}, {%4,%5,%6,%7}, {%8,%9}, {%0,%1,%2,%3};"
        : "+f"(c[0]), "+f"(c[1]), "+f"(c[2]), "+f"(c[3])
        : "r"(a[0]), "r"(a[1]), "r"(a[2]), "r"(a[3]), "r"(b[0]), "r"(b[1]));
}

__device__ __forceinline__ void cp16(uint32_t dst, const void* src) {
    asm volatile("cp.async.cg.shared.global [%0], [%1], 16;" :: "r"(dst), "l"(src));
}

// ---------------------------------------------------------------------------
// Kernel 1: fused QKV projection, tf32 tensor cores (unchanged R2).
// ---------------------------------------------------------------------------
#define GAPAD 36
#define GBPAD 68

__global__ __launch_bounds__(256) void qkv_proj_tf32(
    const float* __restrict__ x,
    const float* __restrict__ Wq, const float* __restrict__ Wk, const float* __restrict__ Wv,
    const float* __restrict__ bq, const float* __restrict__ bk, const float* __restrict__ bv)
{
    __shared__ float As[128][GAPAD];
    __shared__ float Bs[32][GBPAD];

    const int m0  = blockIdx.x * 128;
    const int y   = blockIdx.y;
    const int mat = y / NHEADS;
    const int h   = y % NHEADS;

    const float* W    = (mat == 0 ? Wq : (mat == 1 ? Wk : Wv)) + h * DMODEL * DHEAD;
    const float* bias = (mat == 0 ? bq : (mat == 1 ? bk : bv)) + h * DHEAD;
    float* Out        = (mat == 0 ? Qbuf : (mat == 1 ? Kbuf : Vbuf));

    const int tid  = threadIdx.x;
    const int w    = tid >> 5;
    const int lane = tid & 31;
    const int rA   = lane >> 2;
    const int cA   = lane & 3;
    const int moff = (w & 3) * 32;
    const int noff = (w >> 2) * 32;

    float acc[2][4][4] = {};

    for (int k0 = 0; k0 < DMODEL; k0 += 32) {
        #pragma unroll
        for (int i = 0; i < 4; ++i) {
            int e = tid + i * 256;
            int row = e >> 3, c4 = e & 7;
            float4 v = *reinterpret_cast<const float4*>(x + (size_t)(m0 + row) * DMODEL + k0 + c4 * 4);
            As[row][c4*4+0] = __uint_as_float(f2tf32(v.x));
            As[row][c4*4+1] = __uint_as_float(f2tf32(v.y));
            As[row][c4*4+2] = __uint_as_float(f2tf32(v.z));
            As[row][c4*4+3] = __uint_as_float(f2tf32(v.w));
        }
        #pragma unroll
        for (int i = 0; i < 2; ++i) {
            int e = tid + i * 256;
            int row = e >> 4, c4 = e & 15;
            float4 v = *reinterpret_cast<const float4*>(W + (size_t)(k0 + row) * DHEAD + c4 * 4);
            Bs[row][c4*4+0] = __uint_as_float(f2tf32(v.x));
            Bs[row][c4*4+1] = __uint_as_float(f2tf32(v.y));
            Bs[row][c4*4+2] = __uint_as_float(f2tf32(v.z));
            Bs[row][c4*4+3] = __uint_as_float(f2tf32(v.w));
        }
        __syncthreads();

        #pragma unroll
        for (int kk = 0; kk < 4; ++kk) {
            const int kb = kk * 8;
            uint32_t a[2][4];
            #pragma unroll
            for (int f = 0; f < 2; ++f) {
                a[f][0] = __float_as_uint(As[moff + f*16 + rA    ][kb + cA    ]);
                a[f][1] = __float_as_uint(As[moff + f*16 + rA + 8][kb + cA    ]);
                a[f][2] = __float_as_uint(As[moff + f*16 + rA    ][kb + cA + 4]);
                a[f][3] = __float_as_uint(As[moff + f*16 + rA + 8][kb + cA + 4]);
            }
            uint32_t b[4][2];
            #pragma unroll
            for (int j = 0; j < 4; ++j) {
                b[j][0] = __float_as_uint(Bs[kb + cA    ][noff + j*8 + rA]);
                b[j][1] = __float_as_uint(Bs[kb + cA + 4][noff + j*8 + rA]);
            }
            #pragma unroll
            for (int f = 0; f < 2; ++f)
                #pragma unroll
                for (int j = 0; j < 4; ++j)
                    mma_tf32(acc[f][j], a[f], b[j]);
        }
        __syncthreads();
    }

    const int b  = m0 / SEQ;
    const int s0 = m0 % SEQ;
    #pragma unroll
    for (int f = 0; f < 2; ++f) {
        #pragma unroll
        for (int j = 0; j < 4; ++j) {
            int col = noff + j*8 + 2*cA;
            float b0 = bias[col], b1 = bias[col + 1];
            int s = s0 + moff + f*16 + rA;
            *reinterpret_cast<float2*>(&Out[((size_t)(b*NHEADS + h)*SEQ + s)*DHEAD + col]) =
                make_float2(acc[f][j][0] + b0, acc[f][j][1] + b1);
            *reinterpret_cast<float2*>(&Out[((size_t)(b*NHEADS + h)*SEQ + s + 8)*DHEAD + col]) =
                make_float2(acc[f][j][2] + b0, acc[f][j][3] + b1);
        }
    }
}

// ---------------------------------------------------------------------------
// Kernel 2: causal flash attention v2.
// 256 threads (8 warps), TQ=128 q-rows, TK=64 keys, double-buffered cp.async.
// grid = (SEQ/TQ, B*H); heavy blocks (large q0) scheduled first.
// ---------------------------------------------------------------------------
#define TQ 128
#define TK 64
#define KSTR 68
#define PSTR 68   // P is 16x64 per warp: stride must exceed 64 (was the R3 OOB bug)
#define FLASH_SMEM ((4*TK*KSTR + TQ*PSTR) * 4)   // 104448 bytes

__global__ __launch_bounds__(256) void flash_attn_mma2()
{
    extern __shared__ float dsm[];
    float (*Ksm)[TK][KSTR] = reinterpret_cast<float(*)[TK][KSTR]>(dsm);
    float (*Vsm)[TK][KSTR] = reinterpret_cast<float(*)[TK][KSTR]>(dsm + 2*TK*KSTR);
    float (*Psm)[PSTR]     = reinterpret_cast<float(*)[PSTR]>(dsm + 4*TK*KSTR);

    const int tid  = threadIdx.x;
    const int w    = tid >> 5;
    const int lane = tid & 31;
    const int rA   = lane >> 2;
    const int cA   = lane & 3;
    const int q0   = ((int)gridDim.x - 1 - (int)blockIdx.x) * TQ;  // heavy first
    const int bh   = blockIdx.y;

    const float* Qg = Qbuf + (size_t)(bh*SEQ + q0 + w*16) * DHEAD;
    const float* Kg = Kbuf + (size_t)bh * SEQ * DHEAD;
    const float* Vg = Vbuf + (size_t)bh * SEQ * DHEAD;

    const uint32_t kbase = (uint32_t)__cvta_generic_to_shared(&Ksm[0][0][0]);
    const uint32_t vbase = (uint32_t)__cvta_generic_to_shared(&Vsm[0][0][0]);
    const uint32_t bufstride = TK*KSTR*4;

    // Q fragments (rna tf32, prescaled by 1/8)
    uint32_t qf[8][4];
    #pragma unroll
    for (int ks = 0; ks < 8; ++ks) {
        qf[ks][0] = f2tf32(Qg[(rA    )*DHEAD + ks*8 + cA    ] * 0.125f);
        qf[ks][1] = f2tf32(Qg[(rA + 8)*DHEAD + ks*8 + cA    ] * 0.125f);
        qf[ks][2] = f2tf32(Qg[(rA    )*DHEAD + ks*8 + cA + 4] * 0.125f);
        qf[ks][3] = f2tf32(Qg[(rA + 8)*DHEAD + ks*8 + cA + 4] * 0.125f);
    }

    float o[8][4];
    #pragma unroll
    for (int jt = 0; jt < 8; ++jt) { o[jt][0]=0.f; o[jt][1]=0.f; o[jt][2]=0.f; o[jt][3]=0.f; }
    float m0 = -CUDART_INF_F, m1 = -CUDART_INF_F;
    float l0 = 0.f, l1 = 0.f;

    const int ntiles = q0/TK + 2;

    // prologue: tile 0 -> buf 0
    {
        #pragma unroll
        for (int i = 0; i < 4; ++i) {
            int e = tid + i*256;
            int row = e >> 4, c4 = e & 15;
            uint32_t off = (uint32_t)(row*KSTR + c4*4) * 4u;
            cp16(kbase + off, Kg + (size_t)row*DHEAD + c4*4);
            cp16(vbase + off, Vg + (size_t)row*DHEAD + c4*4);
        }
        asm volatile("cp.async.commit_group;");
    }

    for (int kt = 0; kt < ntiles; ++kt) {
        const int buf = kt & 1;
        if (kt + 1 < ntiles) {
            const float* Ks = Kg + (size_t)(kt+1)*TK*DHEAD;
            const float* Vs = Vg + (size_t)(kt+1)*TK*DHEAD;
            const uint32_t boff = (uint32_t)(buf^1) * bufstride;
            #pragma unroll
            for (int i = 0; i < 4; ++i) {
                int e = tid + i*256;
                int row = e >> 4, c4 = e & 15;
                uint32_t off = boff + (uint32_t)(row*KSTR + c4*4) * 4u;
                cp16(kbase + off, Ks + (size_t)row*DHEAD + c4*4);
                cp16(vbase + off, Vs + (size_t)row*DHEAD + c4*4);
            }
            asm volatile("cp.async.commit_group;");
            asm volatile("cp.async.wait_group 1;");
        } else {
            asm volatile("cp.async.wait_group 0;");
        }
        __syncthreads();

        // Skip compute if this warp's rows are all below the tile's first key
        if (kt*TK <= q0 + w*16 + 15) {
            // S = Q @ K^T : 16 x 64 (8 n-tiles)
            float sc[8][4] = {};
            #pragma unroll
            for (int ks = 0; ks < 8; ++ks) {
                #pragma unroll
                for (int jt = 0; jt < 8; ++jt) {
                    uint32_t b[2];
                    b[0] = __float_as_uint(Ksm[buf][jt*8 + rA][ks*8 + cA    ]);
                    b[1] = __float_as_uint(Ksm[buf][jt*8 + rA][ks*8 + cA + 4]);
                    mma_tf32(sc[jt], qf[ks], b);
                }
            }

            // Causal mask (tiles overlapping/above the diagonal)
            if (kt >= ntiles - 2) {
                const int r0g = q0 + w*16 + rA;
                #pragma unroll
                for (int jt = 0; jt < 8; ++jt) {
                    int key = kt*TK + jt*8 + 2*cA;
                    if (key     > r0g    ) sc[jt][0] = -CUDART_INF_F;
                    if (key + 1 > r0g    ) sc[jt][1] = -CUDART_INF_F;
                    if (key     > r0g + 8) sc[jt][2] = -CUDART_INF_F;
                    if (key + 1 > r0g + 8) sc[jt][3] = -CUDART_INF_F;
                }
            }

            // Online softmax
            float rmax0 = sc[0][0], rmax1 = sc[0][2];
            rmax0 = fmaxf(rmax0, sc[0][1]); rmax1 = fmaxf(rmax1, sc[0][3]);
            #pragma unroll
            for (int jt = 1; jt < 8; ++jt) {
                rmax0 = fmaxf(rmax0, fmaxf(sc[jt][0], sc[jt][1]));
                rmax1 = fmaxf(rmax1, fmaxf(sc[jt][2], sc[jt][3]));
            }
            rmax0 = fmaxf(rmax0, __shfl_xor_sync(0xffffffffu, rmax0, 1));
            rmax0 = fmaxf(rmax0, __shfl_xor_sync(0xffffffffu, rmax0, 2));
            rmax1 = fmaxf(rmax1, __shfl_xor_sync(0xffffffffu, rmax1, 1));
            rmax1 = fmaxf(rmax1, __shfl_xor_sync(0xffffffffu, rmax1, 2));

            float mn0 = fmaxf(m0, rmax0);
            float mn1 = fmaxf(m1, rmax1);
            float f0 = __expf(m0 - mn0);
            float f1 = __expf(m1 - mn1);
            l0 *= f0; l1 *= f1;
            #pragma unroll
            for (int jt = 0; jt < 8; ++jt) {
                o[jt][0] *= f0; o[jt][1] *= f0;
                o[jt][2] *= f1; o[jt][3] *= f1;
            }

            #pragma unroll
            for (int jt = 0; jt < 8; ++jt) {
                float p0 = __expf(sc[jt][0] - mn0);
                float p1 = __expf(sc[jt][1] - mn0);
                float p2 = __expf(sc[jt][2] - mn1);
                float p3 = __expf(sc[jt][3] - mn1);
                l0 += p0 + p1;
                l1 += p2 + p3;
                int col = jt*8 + 2*cA;
                *reinterpret_cast<float2*>(&Psm[w*16 + rA    ][col]) =
                    make_float2(__uint_as_float(f2tf32(p0)), __uint_as_float(f2tf32(p1)));
                *reinterpret_cast<float2*>(&Psm[w*16 + rA + 8][col]) =
                    make_float2(__uint_as_float(f2tf32(p2)), __uint_as_float(f2tf32(p3)));
            }
            m0 = mn0; m1 = mn1;
            __syncwarp();

            // O += P @ V   (P: 16x64, V: 64x64)
            #pragma unroll
            for (int kq = 0; kq < 8; ++kq) {
                uint32_t a[4];
                a[0] = __float_as_uint(Psm[w*16 + rA    ][kq*8 + cA    ]);
                a[1] = __float_as_uint(Psm[w*16 + rA + 8][kq*8 + cA    ]);
                a[2] = __float_as_uint(Psm[w*16 + rA    ][kq*8 + cA + 4]);
                a[3] = __float_as_uint(Psm[w*16 + rA + 8][kq*8 + cA + 4]);
                #pragma unroll
                for (int jt = 0; jt < 8; ++jt) {
                    uint32_t b[2];
                    b[0] = __float_as_uint(Vsm[buf][kq*8 + cA    ][jt*8 + rA]);
                    b[1] = __float_as_uint(Vsm[buf][kq*8 + cA + 4][jt*8 + rA]);
                    mma_tf32(o[jt], a, b);
                }
            }
        }
        __syncthreads();
    }

    l0 += __shfl_xor_sync(0xffffffffu, l0, 1);
    l0 += __shfl_xor_sync(0xffffffffu, l0, 2);
    l1 += __shfl_xor_sync(0xffffffffu, l1, 1);
    l1 += __shfl_xor_sync(0xffffffffu, l1, 2);
    float inv0 = 1.f / l0;
    float inv1 = 1.f / l1;

    float* Zp = Zbuf + (size_t)(bh*SEQ + q0 + w*16) * DHEAD;
    #pragma unroll
    for (int jt = 0; jt < 8; ++jt) {
        int col = jt*8 + 2*cA;
        *reinterpret_cast<float2*>(&Zp[(rA    )*DHEAD + col]) =
            make_float2(o[jt][0]*inv0, o[jt][1]*inv0);
        *reinterpret_cast<float2*>(&Zp[(rA + 8)*DHEAD + col]) =
            make_float2(o[jt][2]*inv1, o[jt][3]*inv1);
    }
}

// ---------------------------------------------------------------------------
// Kernel 3: output projection, tf32 tensor cores (unchanged R2).
// ---------------------------------------------------------------------------
__global__ __launch_bounds__(256) void out_proj_tf32(
    const float* __restrict__ Wo, const float* __restrict__ bo,
    float* __restrict__ out)
{
    __shared__ float As[128][GAPAD];
    __shared__ float Bs[32][GBPAD];

    const int m0 = blockIdx.x * 128;
    const int n0 = blockIdx.y * 64;

    const int tid  = threadIdx.x;
    const int w    = tid >> 5;
    const int lane = tid & 31;
    const int rA   = lane >> 2;
    const int cA   = lane & 3;
    const int moff = (w & 3) * 32;
    const int noff = (w >> 2) * 32;

    const int bb = m0 / SEQ;
    const int s0 = m0 % SEQ;

    float acc[2][4][4] = {};

    for (int k0 = 0; k0 < DMODEL; k0 += 32) {
        const int h  = k0 / DHEAD;
        const int z0 = k0 % DHEAD;
        const float* Zp = Zbuf + ((size_t)(bb*NHEADS + h)*SEQ + s0)*DHEAD + z0;
        #pragma unroll
        for (int i = 0; i < 4; ++i) {
            int e = tid + i * 256;
            int row = e >> 3, c4 = e & 7;
            float4 v = *reinterpret_cast<const float4*>(Zp + (size_t)row * DHEAD + c4 * 4);
            As[row][c4*4+0] = __uint_as_float(f2tf32(v.x));
            As[row][c4*4+1] = __uint_as_float(f2tf32(v.y));
            As[row][c4*4+2] = __uint_as_float(f2tf32(v.z));
            As[row][c4*4+3] = __uint_as_float(f2tf32(v.w));
        }
        #pragma unroll
        for (int i = 0; i < 2; ++i) {
            int e = tid + i * 256;
            int row = e >> 4, c4 = e & 15;
            float4 v = *reinterpret_cast<const float4*>(Wo + (size_t)(k0 + row) * DMODEL + n0 + c4 * 4);
            Bs[row][c4*4+0] = __uint_as_float(f2tf32(v.x));
            Bs[row][c4*4+1] = __uint_as_float(f2tf32(v.y));
            Bs[row][c4*4+2] = __uint_as_float(f2tf32(v.z));
            Bs[row][c4*4+3] = __uint_as_float(f2tf32(v.w));
        }
        __syncthreads();

        #pragma unroll
        for (int kk = 0; kk < 4; ++kk) {
            const int kb = kk * 8;
            uint32_t a[2][4];
            #pragma unroll
            for (int f = 0; f < 2; ++f) {
                a[f][0] = __float_as_uint(As[moff + f*16 + rA    ][kb + cA    ]);
                a[f][1] = __float_as_uint(As[moff + f*16 + rA + 8][kb + cA    ]);
                a[f][2] = __float_as_uint(As[moff + f*16 + rA    ][kb + cA + 4]);
                a[f][3] = __float_as_uint(As[moff + f*16 + rA + 8][kb + cA + 4]);
            }
            uint32_t b[4][2];
            #pragma unroll
            for (int j = 0; j < 4; ++j) {
                b[j][0] = __float_as_uint(Bs[kb + cA    ][noff + j*8 + rA]);
                b[j][1] = __float_as_uint(Bs[kb + cA + 4][noff + j*8 + rA]);
            }
            #pragma unroll
            for (int f = 0; f < 2; ++f)
                #pragma unroll
                for (int j = 0; j < 4; ++j)
                    mma_tf32(acc[f][j], a[f], b[j]);
        }
        __syncthreads();
    }

    #pragma unroll
    for (int f = 0; f < 2; ++f) {
        #pragma unroll
        for (int j = 0; j < 4; ++j) {
            int col = n0 + noff + j*8 + 2*cA;
            float b0 = bo[col], b1 = bo[col + 1];
            int mrow = m0 + moff + f*16 + rA;
            *reinterpret_cast<float2*>(&out[(size_t)mrow * DMODEL + col]) =
                make_float2(acc[f][j][0] + b0, acc[f][j][1] + b1);
            *reinterpret_cast<float2*>(&out[(size_t)(mrow + 8) * DMODEL + col]) =
                make_float2(acc[f][j][2] + b0, acc[f][j][3] + b1);
        }
    }
}

// ---------------------------------------------------------------------------
extern "C" void kernel_launch(void* const* d_in, const int* in_sizes, int n_in,
                              void* d_out, int out_size)
{
    const float* x  = (const float*)d_in[0];
    const float* Wq = (const float*)d_in[1];
    const float* Wk = (const float*)d_in[2];
    const float* Wv = (const float*)d_in[3];
    const float* Wo = (const float*)d_in[4];
    const float* bq = (const float*)d_in[5];
    const float* bk = (const float*)d_in[6];
    const float* bv = (const float*)d_in[7];
    const float* bo = (const float*)d_in[8];
    float* out = (float*)d_out;

    cudaFuncSetAttribute(flash_attn_mma2,
                         cudaFuncAttributeMaxDynamicSharedMemorySize, FLASH_SMEM);

    dim3 g1(MTOT/128, 3*NHEADS);
    qkv_proj_tf32<<<g1, 256>>>(x, Wq, Wk, Wv, bq, bk, bv);

    dim3 g2(SEQ/TQ, BATCH*NHEADS);
    flash_attn_mma2<<<g2, 256, FLASH_SMEM>>>();

    dim3 g3(MTOT/128, DMODEL/64);
    out_proj_tf32<<<g3, 256>>>(Wo, bo, out);
}

// round 7
// speedup vs baseline: 4.1210x; 1.0579x over previous
#include <cuda_runtime.h>
#include <math_constants.h>
#include <cstdint>

// Problem dims
#define BATCH   2
#define SEQ     4096
#define DMODEL  768
#define NHEADS  12
#define DHEAD   64
#define MTOT    (BATCH*SEQ)          // 8192

// Intermediate buffers
__device__ float Qbuf[BATCH*NHEADS*SEQ*DHEAD];
__device__ float Kbuf[BATCH*NHEADS*SEQ*DHEAD];
__device__ float Vbuf[BATCH*NHEADS*SEQ*DHEAD];
__device__ float Zbuf[BATCH*NHEADS*SEQ*DHEAD];   // pre-rounded tf32 bits
__device__ float Xrbuf[MTOT*DMODEL];             // x, rna tf32-rounded
__device__ float WTbuf[NHEADS*3*DHEAD*DMODEL];   // [h][mat*64+n][k], rounded
__device__ float WOTbuf[DMODEL*DMODEL];          // [d][hz], rounded

// ---------------------------------------------------------------------------
// helpers
// ---------------------------------------------------------------------------
__device__ __forceinline__ uint32_t f2tf32(float x) {
    uint32_t r;
    asm("cvt.rna.tf32.f32 %0, %1;" : "=r"(r) : "f"(x));
    return r;
}

__device__ __forceinline__ void mma_tf32(float c[4], const uint32_t a[4], const uint32_t b[2]) {
    asm volatile(
        "mma.sync.aligned.m16n8k8.row.col.f32.tf32.tf32.f32 "
        "{%0,%1,%2,%3}, {%4,%5,%6,%7}, {%8,%9}, {%0,%1,%2,%3};"
        : "+f"(c[0]), "+f"(c[1]), "+f"(c[2]), "+f"(c[3])
        : "r"(a[0]), "r"(a[1]), "r"(a[2]), "r"(a[3]), "r"(b[0]), "r"(b[1]));
}

__device__ __forceinline__ void cp16(uint32_t dst, const void* src) {
    asm volatile("cp.async.cg.shared.global [%0], [%1], 16;" :: "r"(dst), "l"(src));
}

__device__ __forceinline__ uint32_t smem_u32(const void* p) {
    return (uint32_t)__cvta_generic_to_shared(p);
}

// ---------------------------------------------------------------------------
// Prologue kernels: pre-round/transpose operands (rna tf32)
// ---------------------------------------------------------------------------
__global__ __launch_bounds__(256) void xr_kernel(const float* __restrict__ x)
{
    int i = blockIdx.x * 256 + threadIdx.x;
    Xrbuf[i] = __uint_as_float(f2tf32(x[i]));
}

__global__ __launch_bounds__(256) void wt_kernel(
    const float* __restrict__ Wq, const float* __restrict__ Wk, const float* __restrict__ Wv)
{
    int i = blockIdx.x * 256 + threadIdx.x;          // [h][mat*64+n][k]
    int k  = i % DMODEL;
    int r  = i / DMODEL;
    int n  = r & 63;
    int mh = r >> 6;                                  // h*3 + mat
    int mat = mh % 3;
    int h   = mh / 3;
    const float* W = (mat == 0 ? Wq : (mat == 1 ? Wk : Wv));
    WTbuf[i] = __uint_as_float(f2tf32(W[((size_t)h * DMODEL + k) * DHEAD + n]));
}

__global__ __launch_bounds__(256) void wot_kernel(const float* __restrict__ Wo)
{
    int i  = blockIdx.x * 256 + threadIdx.x;          // [d][hz]
    int hz = i % DMODEL;
    int d  = i / DMODEL;
    WOTbuf[i] = __uint_as_float(f2tf32(Wo[(size_t)hz * DMODEL + d]));
}

// ---------------------------------------------------------------------------
// Kernel 1: fused QKV projection, tf32 mma, cp.async double-buffered.
// CTA tile: M=128 x N=192 (Q|K|V for one head). 256 thr, warp tile 64x48.
// grid = (MTOT/128, 12)
// ---------------------------------------------------------------------------
#define QPAD 36
#define QKV_ABYTES (128*QPAD*4)
#define QKV_BBYTES (192*QPAD*4)
#define QKV_SMEM   (2*QKV_ABYTES + 2*QKV_BBYTES)   // 92160

__global__ __launch_bounds__(256) void qkv_tf32_v3(
    const float* __restrict__ bq, const float* __restrict__ bk, const float* __restrict__ bv)
{
    extern __shared__ float sm[];
    float (*As)[128][QPAD] = reinterpret_cast<float(*)[128][QPAD]>(sm);
    float (*Bs)[192][QPAD] = reinterpret_cast<float(*)[192][QPAD]>(sm + 2*128*QPAD);
    const uint32_t abase = smem_u32(&As[0][0][0]);
    const uint32_t bbase = smem_u32(&Bs[0][0][0]);

    const int m0  = blockIdx.x * 128;
    const int h   = blockIdx.y;
    const int tid = threadIdx.x;
    const int w    = tid >> 5;
    const int lane = tid & 31;
    const int rA   = lane >> 2;
    const int cA   = lane & 3;
    const int moff = (w >> 2) * 64;    // 0 or 64
    const int noff = (w & 3) * 48;     // 0,48,96,144

    const float* Ag = Xrbuf + (size_t)m0 * DMODEL;
    const float* Bg = WTbuf + (size_t)h * 192 * DMODEL;

    float acc[4][6][4] = {};

    // issue loads for chunk c into buffer buf
    auto issue = [&](int c, int buf) {
        const int k0 = c * 32;
        #pragma unroll
        for (int i = 0; i < 4; ++i) {
            int e = tid + i * 256, row = e >> 3, c4 = e & 7;
            cp16(abase + (uint32_t)buf * QKV_ABYTES + (uint32_t)(row * QPAD + c4 * 4) * 4u,
                 Ag + (size_t)row * DMODEL + k0 + c4 * 4);
        }
        #pragma unroll
        for (int i = 0; i < 6; ++i) {
            int e = tid + i * 256, row = e >> 3, c4 = e & 7;
            cp16(bbase + (uint32_t)buf * QKV_BBYTES + (uint32_t)(row * QPAD + c4 * 4) * 4u,
                 Bg + (size_t)row * DMODEL + k0 + c4 * 4);
        }
        asm volatile("cp.async.commit_group;");
    };

    issue(0, 0);
    for (int c = 0; c < 24; ++c) {
        const int buf = c & 1;
        if (c < 23) {
            issue(c + 1, buf ^ 1);
            asm volatile("cp.async.wait_group 1;");
        } else {
            asm volatile("cp.async.wait_group 0;");
        }
        __syncthreads();

        #pragma unroll
        for (int kk = 0; kk < 4; ++kk) {
            const int kb = kk * 8;
            uint32_t a[4][4];
            #pragma unroll
            for (int f = 0; f < 4; ++f) {
                a[f][0] = __float_as_uint(As[buf][moff + f*16 + rA    ][kb + cA    ]);
                a[f][1] = __float_as_uint(As[buf][moff + f*16 + rA + 8][kb + cA    ]);
                a[f][2] = __float_as_uint(As[buf][moff + f*16 + rA    ][kb + cA + 4]);
                a[f][3] = __float_as_uint(As[buf][moff + f*16 + rA + 8][kb + cA + 4]);
            }
            uint32_t b[6][2];
            #pragma unroll
            for (int j = 0; j < 6; ++j) {
                b[j][0] = __float_as_uint(Bs[buf][noff + j*8 + rA][kb + cA    ]);
                b[j][1] = __float_as_uint(Bs[buf][noff + j*8 + rA][kb + cA + 4]);
            }
            #pragma unroll
            for (int f = 0; f < 4; ++f)
                #pragma unroll
                for (int j = 0; j < 6; ++j)
                    mma_tf32(acc[f][j], a[f], b[j]);
        }
        __syncthreads();
    }

    // Epilogue
    const int bb = m0 / SEQ;
    const int s0 = m0 % SEQ;
    #pragma unroll
    for (int f = 0; f < 4; ++f) {
        #pragma unroll
        for (int j = 0; j < 6; ++j) {
            int gcol = noff + j*8 + 2*cA;
            int mat  = gcol >> 6;
            int z    = gcol & 63;
            const float* bias = (mat == 0 ? bq : (mat == 1 ? bk : bv)) + h * DHEAD;
            float* Out = (mat == 0 ? Qbuf : (mat == 1 ? Kbuf : Vbuf));
            float b0 = bias[z], b1 = bias[z + 1];
            int s = s0 + moff + f*16 + rA;
            float* r0 = Out + ((size_t)(bb * NHEADS + h) * SEQ + s) * DHEAD + z;
            float* r1 = r0 + 8 * DHEAD;
            *reinterpret_cast<float2*>(r0) = make_float2(acc[f][j][0] + b0, acc[f][j][1] + b1);
            *reinterpret_cast<float2*>(r1) = make_float2(acc[f][j][2] + b0, acc[f][j][3] + b1);
        }
    }
}

// ---------------------------------------------------------------------------
// Kernel 3: output projection, tf32 mma, cp.async double-buffered.
// CTA tile: M=128 x N=128, 256 thr, warp tile 64x32.
// grid = (MTOT/128, 6)
// ---------------------------------------------------------------------------
#define OUT_ABYTES (128*QPAD*4)
#define OUT_BBYTES (128*QPAD*4)
#define OUT_SMEM   (2*OUT_ABYTES + 2*OUT_BBYTES)   // 73728

__global__ __launch_bounds__(256) void out_tf32_v3(
    const float* __restrict__ bo, float* __restrict__ out)
{
    extern __shared__ float sm[];
    float (*As)[128][QPAD] = reinterpret_cast<float(*)[128][QPAD]>(sm);
    float (*Bs)[128][QPAD] = reinterpret_cast<float(*)[128][QPAD]>(sm + 2*128*QPAD);
    const uint32_t abase = smem_u32(&As[0][0][0]);
    const uint32_t bbase = smem_u32(&Bs[0][0][0]);

    const int m0  = blockIdx.x * 128;
    const int n0  = blockIdx.y * 128;
    const int tid = threadIdx.x;
    const int w    = tid >> 5;
    const int lane = tid & 31;
    const int rA   = lane >> 2;
    const int cA   = lane & 3;
    const int moff = (w >> 2) * 64;    // 0 or 64
    const int noff = (w & 3) * 32;     // 0,32,64,96

    const int bb = m0 / SEQ;
    const int s0 = m0 % SEQ;

    float acc[4][4][4] = {};

    auto issue = [&](int c, int buf) {
        const int k0 = c * 32;
        const int hh = k0 / DHEAD;
        const int z0 = k0 % DHEAD;
        const float* Ag = Zbuf + ((size_t)(bb * NHEADS + hh) * SEQ + s0) * DHEAD + z0;
        #pragma unroll
        for (int i = 0; i < 4; ++i) {
            int e = tid + i * 256, row = e >> 3, c4 = e & 7;
            cp16(abase + (uint32_t)buf * OUT_ABYTES + (uint32_t)(row * QPAD + c4 * 4) * 4u,
                 Ag + (size_t)row * DHEAD + c4 * 4);
        }
        #pragma unroll
        for (int i = 0; i < 4; ++i) {
            int e = tid + i * 256, row = e >> 3, c4 = e & 7;
            cp16(bbase + (uint32_t)buf * OUT_BBYTES + (uint32_t)(row * QPAD + c4 * 4) * 4u,
                 WOTbuf + (size_t)(n0 + row) * DMODEL + k0 + c4 * 4);
        }
        asm volatile("cp.async.commit_group;");
    };

    issue(0, 0);
    for (int c = 0; c < 24; ++c) {
        const int buf = c & 1;
        if (c < 23) {
            issue(c + 1, buf ^ 1);
            asm volatile("cp.async.wait_group 1;");
        } else {
            asm volatile("cp.async.wait_group 0;");
        }
        __syncthreads();

        #pragma unroll
        for (int kk = 0; kk < 4; ++kk) {
            const int kb = kk * 8;
            uint32_t a[4][4];
            #pragma unroll
            for (int f = 0; f < 4; ++f) {
                a[f][0] = __float_as_uint(As[buf][moff + f*16 + rA    ][kb + cA    ]);
                a[f][1] = __float_as_uint(As[buf][moff + f*16 + rA + 8][kb + cA    ]);
                a[f][2] = __float_as_uint(As[buf][moff + f*16 + rA    ][kb + cA + 4]);
                a[f][3] = __float_as_uint(As[buf][moff + f*16 + rA + 8][kb + cA + 4]);
            }
            uint32_t b[4][2];
            #pragma unroll
            for (int j = 0; j < 4; ++j) {
                b[j][0] = __float_as_uint(Bs[buf][noff + j*8 + rA][kb + cA    ]);
                b[j][1] = __float_as_uint(Bs[buf][noff + j*8 + rA][kb + cA + 4]);
            }
            #pragma unroll
            for (int f = 0; f < 4; ++f)
                #pragma unroll
                for (int j = 0; j < 4; ++j)
                    mma_tf32(acc[f][j], a[f], b[j]);
        }
        __syncthreads();
    }

    #pragma unroll
    for (int f = 0; f < 4; ++f) {
        #pragma unroll
        for (int j = 0; j < 4; ++j) {
            int col = n0 + noff + j*8 + 2*cA;
            float b0 = bo[col], b1 = bo[col + 1];
            int mrow = m0 + moff + f*16 + rA;
            *reinterpret_cast<float2*>(&out[(size_t)mrow * DMODEL + col]) =
                make_float2(acc[f][j][0] + b0, acc[f][j][1] + b1);
            *reinterpret_cast<float2*>(&out[(size_t)(mrow + 8) * DMODEL + col]) =
                make_float2(acc[f][j][2] + b0, acc[f][j][3] + b1);
        }
    }
}

// ---------------------------------------------------------------------------
// Kernel 2: causal flash attention (R5 structure; stores Z pre-rounded).
// ---------------------------------------------------------------------------
#define TQ 128
#define TK 64
#define KSTR 68
#define PSTR 68
#define FLASH_SMEM ((4*TK*KSTR + TQ*PSTR) * 4)   // 104448 bytes

__global__ __launch_bounds__(256) void flash_attn_mma2()
{
    extern __shared__ float dsm[];
    float (*Ksm)[TK][KSTR] = reinterpret_cast<float(*)[TK][KSTR]>(dsm);
    float (*Vsm)[TK][KSTR] = reinterpret_cast<float(*)[TK][KSTR]>(dsm + 2*TK*KSTR);
    float (*Psm)[PSTR]     = reinterpret_cast<float(*)[PSTR]>(dsm + 4*TK*KSTR);

    const int tid  = threadIdx.x;
    const int w    = tid >> 5;
    const int lane = tid & 31;
    const int rA   = lane >> 2;
    const int cA   = lane & 3;
    const int q0   = ((int)gridDim.x - 1 - (int)blockIdx.x) * TQ;
    const int bh   = blockIdx.y;

    const float* Qg = Qbuf + (size_t)(bh*SEQ + q0 + w*16) * DHEAD;
    const float* Kg = Kbuf + (size_t)bh * SEQ * DHEAD;
    const float* Vg = Vbuf + (size_t)bh * SEQ * DHEAD;

    const uint32_t kbase = smem_u32(&Ksm[0][0][0]);
    const uint32_t vbase = smem_u32(&Vsm[0][0][0]);
    const uint32_t bufstride = TK*KSTR*4;

    uint32_t qf[8][4];
    #pragma unroll
    for (int ks = 0; ks < 8; ++ks) {
        qf[ks][0] = f2tf32(Qg[(rA    )*DHEAD + ks*8 + cA    ] * 0.125f);
        qf[ks][1] = f2tf32(Qg[(rA + 8)*DHEAD + ks*8 + cA    ] * 0.125f);
        qf[ks][2] = f2tf32(Qg[(rA    )*DHEAD + ks*8 + cA + 4] * 0.125f);
        qf[ks][3] = f2tf32(Qg[(rA + 8)*DHEAD + ks*8 + cA + 4] * 0.125f);
    }

    float o[8][4];
    #pragma unroll
    for (int jt = 0; jt < 8; ++jt) { o[jt][0]=0.f; o[jt][1]=0.f; o[jt][2]=0.f; o[jt][3]=0.f; }
    float m0 = -CUDART_INF_F, m1 = -CUDART_INF_F;
    float l0 = 0.f, l1 = 0.f;

    const int ntiles = q0/TK + 2;

    {
        #pragma unroll
        for (int i = 0; i < 4; ++i) {
            int e = tid + i*256;
            int row = e >> 4, c4 = e & 15;
            uint32_t off = (uint32_t)(row*KSTR + c4*4) * 4u;
            cp16(kbase + off, Kg + (size_t)row*DHEAD + c4*4);
            cp16(vbase + off, Vg + (size_t)row*DHEAD + c4*4);
        }
        asm volatile("cp.async.commit_group;");
    }

    for (int kt = 0; kt < ntiles; ++kt) {
        const int buf = kt & 1;
        if (kt + 1 < ntiles) {
            const float* Ks = Kg + (size_t)(kt+1)*TK*DHEAD;
            const float* Vs = Vg + (size_t)(kt+1)*TK*DHEAD;
            const uint32_t boff = (uint32_t)(buf^1) * bufstride;
            #pragma unroll
            for (int i = 0; i < 4; ++i) {
                int e = tid + i*256;
                int row = e >> 4, c4 = e & 15;
                uint32_t off = boff + (uint32_t)(row*KSTR + c4*4) * 4u;
                cp16(kbase + off, Ks + (size_t)row*DHEAD + c4*4);
                cp16(vbase + off, Vs + (size_t)row*DHEAD + c4*4);
            }
            asm volatile("cp.async.commit_group;");
            asm volatile("cp.async.wait_group 1;");
        } else {
            asm volatile("cp.async.wait_group 0;");
        }
        __syncthreads();

        if (kt*TK <= q0 + w*16 + 15) {
            float sc[8][4] = {};
            #pragma unroll
            for (int ks = 0; ks < 8; ++ks) {
                #pragma unroll
                for (int jt = 0; jt < 8; ++jt) {
                    uint32_t b[2];
                    b[0] = __float_as_uint(Ksm[buf][jt*8 + rA][ks*8 + cA    ]);
                    b[1] = __float_as_uint(Ksm[buf][jt*8 + rA][ks*8 + cA + 4]);
                    mma_tf32(sc[jt], qf[ks], b);
                }
            }

            if (kt >= ntiles - 2) {
                const int r0g = q0 + w*16 + rA;
                #pragma unroll
                for (int jt = 0; jt < 8; ++jt) {
                    int key = kt*TK + jt*8 + 2*cA;
                    if (key     > r0g    ) sc[jt][0] = -CUDART_INF_F;
                    if (key + 1 > r0g    ) sc[jt][1] = -CUDART_INF_F;
                    if (key     > r0g + 8) sc[jt][2] = -CUDART_INF_F;
                    if (key + 1 > r0g + 8) sc[jt][3] = -CUDART_INF_F;
                }
            }

            float rmax0 = sc[0][0], rmax1 = sc[0][2];
            rmax0 = fmaxf(rmax0, sc[0][1]); rmax1 = fmaxf(rmax1, sc[0][3]);
            #pragma unroll
            for (int jt = 1; jt < 8; ++jt) {
                rmax0 = fmaxf(rmax0, fmaxf(sc[jt][0], sc[jt][1]));
                rmax1 = fmaxf(rmax1, fmaxf(sc[jt][2], sc[jt][3]));
            }
            rmax0 = fmaxf(rmax0, __shfl_xor_sync(0xffffffffu, rmax0, 1));
            rmax0 = fmaxf(rmax0, __shfl_xor_sync(0xffffffffu, rmax0, 2));
            rmax1 = fmaxf(rmax1, __shfl_xor_sync(0xffffffffu, rmax1, 1));
            rmax1 = fmaxf(rmax1, __shfl_xor_sync(0xffffffffu, rmax1, 2));

            float mn0 = fmaxf(m0, rmax0);
            float mn1 = fmaxf(m1, rmax1);
            float f0 = __expf(m0 - mn0);
            float f1 = __expf(m1 - mn1);
            l0 *= f0; l1 *= f1;
            #pragma unroll
            for (int jt = 0; jt < 8; ++jt) {
                o[jt][0] *= f0; o[jt][1] *= f0;
                o[jt][2] *= f1; o[jt][3] *= f1;
            }

            #pragma unroll
            for (int jt = 0; jt < 8; ++jt) {
                float p0 = __expf(sc[jt][0] - mn0);
                float p1 = __expf(sc[jt][1] - mn0);
                float p2 = __expf(sc[jt][2] - mn1);
                float p3 = __expf(sc[jt][3] - mn1);
                l0 += p0 + p1;
                l1 += p2 + p3;
                int col = jt*8 + 2*cA;
                *reinterpret_cast<float2*>(&Psm[w*16 + rA    ][col]) =
                    make_float2(__uint_as_float(f2tf32(p0)), __uint_as_float(f2tf32(p1)));
                *reinterpret_cast<float2*>(&Psm[w*16 + rA + 8][col]) =
                    make_float2(__uint_as_float(f2tf32(p2)), __uint_as_float(f2tf32(p3)));
            }
            m0 = mn0; m1 = mn1;
            __syncwarp();

            #pragma unroll
            for (int kq = 0; kq < 8; ++kq) {
                uint32_t a[4];
                a[0] = __float_as_uint(Psm[w*16 + rA    ][kq*8 + cA    ]);
                a[1] = __float_as_uint(Psm[w*16 + rA + 8][kq*8 + cA    ]);
                a[2] = __float_as_uint(Psm[w*16 + rA    ][kq*8 + cA + 4]);
                a[3] = __float_as_uint(Psm[w*16 + rA + 8][kq*8 + cA + 4]);
                #pragma unroll
                for (int jt = 0; jt < 8; ++jt) {
                    uint32_t b[2];
                    b[0] = __float_as_uint(Vsm[buf][kq*8 + cA    ][jt*8 + rA]);
                    b[1] = __float_as_uint(Vsm[buf][kq*8 + cA + 4][jt*8 + rA]);
                    mma_tf32(o[jt], a, b);
                }
            }
        }
        __syncthreads();
    }

    l0 += __shfl_xor_sync(0xffffffffu, l0, 1);
    l0 += __shfl_xor_sync(0xffffffffu, l0, 2);
    l1 += __shfl_xor_sync(0xffffffffu, l1, 1);
    l1 += __shfl_xor_sync(0xffffffffu, l1, 2);
    float inv0 = 1.f / l0;
    float inv1 = 1.f / l1;

    // Store Z pre-rounded (rna tf32 bits) so out_proj can cp.async it directly.
    float* Zp = Zbuf + (size_t)(bh*SEQ + q0 + w*16) * DHEAD;
    #pragma unroll
    for (int jt = 0; jt < 8; ++jt) {
        int col = jt*8 + 2*cA;
        *reinterpret_cast<float2*>(&Zp[(rA    )*DHEAD + col]) =
            make_float2(__uint_as_float(f2tf32(o[jt][0]*inv0)),
                        __uint_as_float(f2tf32(o[jt][1]*inv0)));
        *reinterpret_cast<float2*>(&Zp[(rA + 8)*DHEAD + col]) =
            make_float2(__uint_as_float(f2tf32(o[jt][2]*inv1)),
                        __uint_as_float(f2tf32(o[jt][3]*inv1)));
    }
}

// ---------------------------------------------------------------------------
extern "C" void kernel_launch(void* const* d_in, const int* in_sizes, int n_in,
                              void* d_out, int out_size)
{
    const float* x  = (const float*)d_in[0];
    const float* Wq = (const float*)d_in[1];
    const float* Wk = (const float*)d_in[2];
    const float* Wv = (const float*)d_in[3];
    const float* Wo = (const float*)d_in[4];
    const float* bq = (const float*)d_in[5];
    const float* bk = (const float*)d_in[6];
    const float* bv = (const float*)d_in[7];
    const float* bo = (const float*)d_in[8];
    float* out = (float*)d_out;

    cudaFuncSetAttribute(flash_attn_mma2, cudaFuncAttributeMaxDynamicSharedMemorySize, FLASH_SMEM);
    cudaFuncSetAttribute(qkv_tf32_v3,     cudaFuncAttributeMaxDynamicSharedMemorySize, QKV_SMEM);
    cudaFuncSetAttribute(out_tf32_v3,     cudaFuncAttributeMaxDynamicSharedMemorySize, OUT_SMEM);

    xr_kernel<<<MTOT*DMODEL/256, 256>>>(x);
    wt_kernel<<<NHEADS*3*DHEAD*DMODEL/256, 256>>>(Wq, Wk, Wv);
    wot_kernel<<<DMODEL*DMODEL/256, 256>>>(Wo);

    dim3 g1(MTOT/128, NHEADS);
    qkv_tf32_v3<<<g1, 256, QKV_SMEM>>>(bq, bk, bv);

    dim3 g2(SEQ/TQ, BATCH*NHEADS);
    flash_attn_mma2<<<g2, 256, FLASH_SMEM>>>();

    dim3 g3(MTOT/128, DMODEL/128);
    out_tf32_v3<<<g3, 256, OUT_SMEM>>>(bo, out);
}

// round 8
// speedup vs baseline: 8.3481x; 2.0258x over previous
#include <cuda_runtime.h>
#include <cuda_fp16.h>
#include <math_constants.h>
#include <cstdint>

// Problem dims
#define BATCH   2
#define SEQ     4096
#define DMODEL  768
#define NHEADS  12
#define DHEAD   64
#define MTOT    (BATCH*SEQ)          // 8192

// fp16 operand buffers
__device__ __half Xh[MTOT*DMODEL];                 // x, fp16
__device__ __half WTh[NHEADS*3*DHEAD*DMODEL];      // [h][mat*64+n][k]
__device__ __half WOTh[DMODEL*DMODEL];             // [d][hz]
__device__ __half Qh[BATCH*NHEADS*SEQ*DHEAD];      // pre-scaled by 1/8
__device__ __half Kh[BATCH*NHEADS*SEQ*DHEAD];
__device__ __half Vh[BATCH*NHEADS*SEQ*DHEAD];
__device__ __half Zh[BATCH*NHEADS*SEQ*DHEAD];

// ---------------------------------------------------------------------------
// helpers
// ---------------------------------------------------------------------------
__device__ __forceinline__ void mma_f16(float c[4], const uint32_t a[4], const uint32_t b[2]) {
    asm volatile(
        "mma.sync.aligned.m16n8k16.row.col.f32.f16.f16.f32 "
        "{%0,%1,%2,%3}, {%4,%5,%6,%7}, {%8,%9}, {%0,%1,%2,%3};"
        : "+f"(c[0]), "+f"(c[1]), "+f"(c[2]), "+f"(c[3])
        : "r"(a[0]), "r"(a[1]), "r"(a[2]), "r"(a[3]), "r"(b[0]), "r"(b[1]));
}

__device__ __forceinline__ void cp16(uint32_t dst, const void* src) {
    asm volatile("cp.async.cg.shared.global [%0], [%1], 16;" :: "r"(dst), "l"(src));
}

__device__ __forceinline__ uint32_t smem_u32(const void* p) {
    return (uint32_t)__cvta_generic_to_shared(p);
}

__device__ __forceinline__ uint32_t ldu32(const __half* p) {
    return *reinterpret_cast<const uint32_t*>(p);
}

__device__ __forceinline__ uint32_t h2bits(float x, float y) {
    __half2 v = __floats2half2_rn(x, y);
    return *reinterpret_cast<uint32_t*>(&v);
}

// ---------------------------------------------------------------------------
// Prologues: fp32 -> fp16 conversions / transposes
// ---------------------------------------------------------------------------
__global__ __launch_bounds__(256) void xh_kernel(const float* __restrict__ x)
{
    int i = blockIdx.x * 256 + threadIdx.x;
    Xh[i] = __float2half_rn(x[i]);
}

__global__ __launch_bounds__(256) void wth_kernel(
    const float* __restrict__ Wq, const float* __restrict__ Wk, const float* __restrict__ Wv)
{
    int i = blockIdx.x * 256 + threadIdx.x;          // [h][mat*64+n][k]
    int k  = i % DMODEL;
    int r  = i / DMODEL;
    int n  = r & 63;
    int mh = r >> 6;                                  // h*3 + mat
    int mat = mh % 3;
    int h   = mh / 3;
    const float* W = (mat == 0 ? Wq : (mat == 1 ? Wk : Wv));
    WTh[i] = __float2half_rn(W[((size_t)h * DMODEL + k) * DHEAD + n]);
}

__global__ __launch_bounds__(256) void woth_kernel(const float* __restrict__ Wo)
{
    int i  = blockIdx.x * 256 + threadIdx.x;          // [d][hz]
    int hz = i % DMODEL;
    int d  = i / DMODEL;
    WOTh[i] = __float2half_rn(Wo[(size_t)hz * DMODEL + d]);
}

// ---------------------------------------------------------------------------
// Kernel 1: fused QKV projection, fp16 mma, cp.async double-buffered.
// CTA tile M=128 x N=192, K-chunk 64 (12 chunks). 256 thr, warp tile 64x48.
// grid = (MTOT/128, 12)
// ---------------------------------------------------------------------------
#define HPAD 72                          // halves per smem row (144B)
#define QKV_AH (128*HPAD)                // halves per A buffer
#define QKV_BH (192*HPAD)
#define QKV_SMEM ((2*QKV_AH + 2*QKV_BH) * 2)   // 92160 B

__global__ __launch_bounds__(256) void qkv_f16(
    const float* __restrict__ bq, const float* __restrict__ bk, const float* __restrict__ bv)
{
    extern __shared__ __half hsm[];
    __half* As = hsm;                    // 2 bufs
    __half* Bs = hsm + 2*QKV_AH;         // 2 bufs
    const uint32_t abase = smem_u32(As);
    const uint32_t bbase = smem_u32(Bs);

    const int m0  = blockIdx.x * 128;
    const int h   = blockIdx.y;
    const int tid = threadIdx.x;
    const int w    = tid >> 5;
    const int lane = tid & 31;
    const int rA   = lane >> 2;
    const int cA   = lane & 3;
    const int moff = (w >> 2) * 64;
    const int noff = (w & 3) * 48;

    const __half* Ag = Xh + (size_t)m0 * DMODEL;
    const __half* Bg = WTh + (size_t)h * 192 * DMODEL;

    float acc[4][6][4] = {};

    auto issue = [&](int c, int buf) {
        const int k0 = c * 64;
        #pragma unroll
        for (int i = 0; i < 4; ++i) {
            int e = tid + i * 256, row = e >> 3, seg = e & 7;
            cp16(abase + (uint32_t)(buf * QKV_AH + row * HPAD + seg * 8) * 2u,
                 Ag + (size_t)row * DMODEL + k0 + seg * 8);
        }
        #pragma unroll
        for (int i = 0; i < 6; ++i) {
            int e = tid + i * 256, row = e >> 3, seg = e & 7;
            cp16(bbase + (uint32_t)(buf * QKV_BH + row * HPAD + seg * 8) * 2u,
                 Bg + (size_t)row * DMODEL + k0 + seg * 8);
        }
        asm volatile("cp.async.commit_group;");
    };

    issue(0, 0);
    for (int c = 0; c < 12; ++c) {
        const int buf = c & 1;
        if (c < 11) {
            issue(c + 1, buf ^ 1);
            asm volatile("cp.async.wait_group 1;");
        } else {
            asm volatile("cp.async.wait_group 0;");
        }
        __syncthreads();

        const __half* Ab = As + buf * QKV_AH;
        const __half* Bb = Bs + buf * QKV_BH;
        #pragma unroll
        for (int ks = 0; ks < 4; ++ks) {
            const int kb = ks * 16;
            uint32_t a[4][4];
            #pragma unroll
            for (int f = 0; f < 4; ++f) {
                const __half* r0 = Ab + (moff + f*16 + rA) * HPAD + kb + 2*cA;
                const __half* r1 = r0 + 8 * HPAD;
                a[f][0] = ldu32(r0);
                a[f][1] = ldu32(r1);
                a[f][2] = ldu32(r0 + 8);
                a[f][3] = ldu32(r1 + 8);
            }
            uint32_t b[6][2];
            #pragma unroll
            for (int j = 0; j < 6; ++j) {
                const __half* rb = Bb + (noff + j*8 + rA) * HPAD + kb + 2*cA;
                b[j][0] = ldu32(rb);
                b[j][1] = ldu32(rb + 8);
            }
            #pragma unroll
            for (int f = 0; f < 4; ++f)
                #pragma unroll
                for (int j = 0; j < 6; ++j)
                    mma_f16(acc[f][j], a[f], b[j]);
        }
        __syncthreads();
    }

    // Epilogue: bias, Q pre-scaled by 1/8, store fp16
    const int bb = m0 / SEQ;
    const int s0 = m0 % SEQ;
    #pragma unroll
    for (int f = 0; f < 4; ++f) {
        #pragma unroll
        for (int j = 0; j < 6; ++j) {
            int gcol = noff + j*8 + 2*cA;
            int mat  = gcol >> 6;
            int z    = gcol & 63;
            const float* bias = (mat == 0 ? bq : (mat == 1 ? bk : bv)) + h * DHEAD;
            __half* Out = (mat == 0 ? Qh : (mat == 1 ? Kh : Vh));
            float sc = (mat == 0) ? 0.125f : 1.0f;
            float b0 = bias[z], b1 = bias[z + 1];
            int s = s0 + moff + f*16 + rA;
            __half* r0 = Out + ((size_t)(bb * NHEADS + h) * SEQ + s) * DHEAD + z;
            __half* r1 = r0 + 8 * DHEAD;
            *reinterpret_cast<uint32_t*>(r0) = h2bits((acc[f][j][0] + b0) * sc, (acc[f][j][1] + b1) * sc);
            *reinterpret_cast<uint32_t*>(r1) = h2bits((acc[f][j][2] + b0) * sc, (acc[f][j][3] + b1) * sc);
        }
    }
}

// ---------------------------------------------------------------------------
// Kernel 2: causal flash attention, fp16 mma + ldmatrix.trans for V.
// 256 thr (8 warps), TQ=128, TK=64, double-buffered cp.async.
// grid = (SEQ/TQ, B*H), heavy blocks first.
// ---------------------------------------------------------------------------
#define TQ 128
#define TK 64
#define KVH (TK*HPAD)                        // halves per K or V buffer
#define FLASH_SMEM ((4*KVH + TQ*HPAD) * 2)   // 55296 B

__global__ __launch_bounds__(256) void flash_f16()
{
    extern __shared__ __half hsm[];
    __half* Ks = hsm;                    // 2 bufs
    __half* Vs = hsm + 2*KVH;            // 2 bufs
    __half* Ps = hsm + 4*KVH;            // TQ x HPAD
    const uint32_t kbase = smem_u32(Ks);
    const uint32_t vbase = smem_u32(Vs);

    const int tid  = threadIdx.x;
    const int w    = tid >> 5;
    const int lane = tid & 31;
    const int rA   = lane >> 2;
    const int cA   = lane & 3;
    const int q0   = ((int)gridDim.x - 1 - (int)blockIdx.x) * TQ;
    const int bh   = blockIdx.y;

    const __half* Qg = Qh + (size_t)(bh*SEQ + q0 + w*16) * DHEAD;
    const __half* Kg = Kh + (size_t)bh * SEQ * DHEAD;
    const __half* Vg = Vh + (size_t)bh * SEQ * DHEAD;

    // Q fragments: 4 k16-steps
    uint32_t qf[4][4];
    #pragma unroll
    for (int ks = 0; ks < 4; ++ks) {
        const __half* r0 = Qg + rA * DHEAD + ks*16 + 2*cA;
        const __half* r1 = r0 + 8 * DHEAD;
        qf[ks][0] = ldu32(r0);
        qf[ks][1] = ldu32(r1);
        qf[ks][2] = ldu32(r0 + 8);
        qf[ks][3] = ldu32(r1 + 8);
    }

    float o[8][4];
    #pragma unroll
    for (int jt = 0; jt < 8; ++jt) { o[jt][0]=0.f; o[jt][1]=0.f; o[jt][2]=0.f; o[jt][3]=0.f; }
    float m0 = -CUDART_INF_F, m1 = -CUDART_INF_F;
    float l0 = 0.f, l1 = 0.f;

    const int ntiles = q0/TK + 2;

    auto issue = [&](int kt, int buf) {
        #pragma unroll
        for (int i = 0; i < 2; ++i) {
            int e = tid + i * 256, row = e >> 3, seg = e & 7;
            cp16(kbase + (uint32_t)(buf * KVH + row * HPAD + seg * 8) * 2u,
                 Kg + (size_t)(kt*TK + row) * DHEAD + seg * 8);
        }
        #pragma unroll
        for (int i = 0; i < 2; ++i) {
            int e = tid + i * 256, row = e >> 3, seg = e & 7;
            cp16(vbase + (uint32_t)(buf * KVH + row * HPAD + seg * 8) * 2u,
                 Vg + (size_t)(kt*TK + row) * DHEAD + seg * 8);
        }
        asm volatile("cp.async.commit_group;");
    };

    issue(0, 0);
    for (int kt = 0; kt < ntiles; ++kt) {
        const int buf = kt & 1;
        if (kt + 1 < ntiles) {
            issue(kt + 1, buf ^ 1);
            asm volatile("cp.async.wait_group 1;");
        } else {
            asm volatile("cp.async.wait_group 0;");
        }
        __syncthreads();

        if (kt*TK <= q0 + w*16 + 15) {
            const __half* Kb = Ks + buf * KVH;
            // S = Q @ K^T : 16x64
            float sc[8][4] = {};
            #pragma unroll
            for (int ks = 0; ks < 4; ++ks) {
                #pragma unroll
                for (int jt = 0; jt < 8; ++jt) {
                    const __half* rb = Kb + (jt*8 + rA) * HPAD + ks*16 + 2*cA;
                    uint32_t b[2];
                    b[0] = ldu32(rb);
                    b[1] = ldu32(rb + 8);
                    mma_f16(sc[jt], qf[ks], b);
                }
            }

            if (kt >= ntiles - 2) {
                const int r0g = q0 + w*16 + rA;
                #pragma unroll
                for (int jt = 0; jt < 8; ++jt) {
                    int key = kt*TK + jt*8 + 2*cA;
                    if (key     > r0g    ) sc[jt][0] = -CUDART_INF_F;
                    if (key + 1 > r0g    ) sc[jt][1] = -CUDART_INF_F;
                    if (key     > r0g + 8) sc[jt][2] = -CUDART_INF_F;
                    if (key + 1 > r0g + 8) sc[jt][3] = -CUDART_INF_F;
                }
            }

            float rmax0 = fmaxf(sc[0][0], sc[0][1]), rmax1 = fmaxf(sc[0][2], sc[0][3]);
            #pragma unroll
            for (int jt = 1; jt < 8; ++jt) {
                rmax0 = fmaxf(rmax0, fmaxf(sc[jt][0], sc[jt][1]));
                rmax1 = fmaxf(rmax1, fmaxf(sc[jt][2], sc[jt][3]));
            }
            rmax0 = fmaxf(rmax0, __shfl_xor_sync(0xffffffffu, rmax0, 1));
            rmax0 = fmaxf(rmax0, __shfl_xor_sync(0xffffffffu, rmax0, 2));
            rmax1 = fmaxf(rmax1, __shfl_xor_sync(0xffffffffu, rmax1, 1));
            rmax1 = fmaxf(rmax1, __shfl_xor_sync(0xffffffffu, rmax1, 2));

            float mn0 = fmaxf(m0, rmax0);
            float mn1 = fmaxf(m1, rmax1);
            float f0 = __expf(m0 - mn0);
            float f1 = __expf(m1 - mn1);
            l0 *= f0; l1 *= f1;
            #pragma unroll
            for (int jt = 0; jt < 8; ++jt) {
                o[jt][0] *= f0; o[jt][1] *= f0;
                o[jt][2] *= f1; o[jt][3] *= f1;
            }

            #pragma unroll
            for (int jt = 0; jt < 8; ++jt) {
                float p0 = __expf(sc[jt][0] - mn0);
                float p1 = __expf(sc[jt][1] - mn0);
                float p2 = __expf(sc[jt][2] - mn1);
                float p3 = __expf(sc[jt][3] - mn1);
                l0 += p0 + p1;
                l1 += p2 + p3;
                __half* pr = Ps + (w*16 + rA) * HPAD + jt*8 + 2*cA;
                *reinterpret_cast<uint32_t*>(pr)            = h2bits(p0, p1);
                *reinterpret_cast<uint32_t*>(pr + 8*HPAD)   = h2bits(p2, p3);
            }
            m0 = mn0; m1 = mn1;
            __syncwarp();

            // O += P @ V  via ldmatrix.x4.trans on V
            const uint32_t vb = vbase + (uint32_t)(buf * KVH) * 2u;
            #pragma unroll
            for (int kq = 0; kq < 4; ++kq) {
                const __half* pa = Ps + (w*16 + rA) * HPAD + kq*16 + 2*cA;
                uint32_t a[4];
                a[0] = ldu32(pa);
                a[1] = ldu32(pa + 8*HPAD);
                a[2] = ldu32(pa + 8);
                a[3] = ldu32(pa + 8*HPAD + 8);
                #pragma unroll
                for (int jp = 0; jp < 4; ++jp) {
                    int lrow = kq*16 + (lane & 15);
                    int lcol = jp*16 + ((lane & 16) >> 1);
                    uint32_t addr = vb + (uint32_t)(lrow * HPAD + lcol) * 2u;
                    uint32_t r0, r1, r2, r3;
                    asm volatile(
                        "ldmatrix.sync.aligned.m8n8.x4.trans.shared.b16 {%0,%1,%2,%3}, [%4];"
                        : "=r"(r0), "=r"(r1), "=r"(r2), "=r"(r3) : "r"(addr));
                    uint32_t b0[2] = {r0, r1};
                    uint32_t b1[2] = {r2, r3};
                    mma_f16(o[2*jp    ], a, b0);
                    mma_f16(o[2*jp + 1], a, b1);
                }
            }
        }
        __syncthreads();
    }

    l0 += __shfl_xor_sync(0xffffffffu, l0, 1);
    l0 += __shfl_xor_sync(0xffffffffu, l0, 2);
    l1 += __shfl_xor_sync(0xffffffffu, l1, 1);
    l1 += __shfl_xor_sync(0xffffffffu, l1, 2);
    float inv0 = 1.f / l0;
    float inv1 = 1.f / l1;

    __half* Zp = Zh + (size_t)(bh*SEQ + q0 + w*16) * DHEAD;
    #pragma unroll
    for (int jt = 0; jt < 8; ++jt) {
        int col = jt*8 + 2*cA;
        *reinterpret_cast<uint32_t*>(Zp + rA * DHEAD + col) =
            h2bits(o[jt][0]*inv0, o[jt][1]*inv0);
        *reinterpret_cast<uint32_t*>(Zp + (rA + 8) * DHEAD + col) =
            h2bits(o[jt][2]*inv1, o[jt][3]*inv1);
    }
}

// ---------------------------------------------------------------------------
// Kernel 3: output projection, fp16 mma. CTA 128x128, K-chunk 64 (= one head).
// grid = (MTOT/128, 6)
// ---------------------------------------------------------------------------
#define OUT_AH (128*HPAD)
#define OUT_BH (128*HPAD)
#define OUT_SMEM ((2*OUT_AH + 2*OUT_BH) * 2)   // 73728 B

__global__ __launch_bounds__(256) void out_f16(
    const float* __restrict__ bo, float* __restrict__ out)
{
    extern __shared__ __half hsm[];
    __half* As = hsm;
    __half* Bs = hsm + 2*OUT_AH;
    const uint32_t abase = smem_u32(As);
    const uint32_t bbase = smem_u32(Bs);

    const int m0  = blockIdx.x * 128;
    const int n0  = blockIdx.y * 128;
    const int tid = threadIdx.x;
    const int w    = tid >> 5;
    const int lane = tid & 31;
    const int rA   = lane >> 2;
    const int cA   = lane & 3;
    const int moff = (w >> 2) * 64;
    const int noff = (w & 3) * 32;

    const int bb = m0 / SEQ;
    const int s0 = m0 % SEQ;

    float acc[4][4][4] = {};

    auto issue = [&](int c, int buf) {
        const __half* Ag = Zh + ((size_t)(bb * NHEADS + c) * SEQ + s0) * DHEAD;
        #pragma unroll
        for (int i = 0; i < 4; ++i) {
            int e = tid + i * 256, row = e >> 3, seg = e & 7;
            cp16(abase + (uint32_t)(buf * OUT_AH + row * HPAD + seg * 8) * 2u,
                 Ag + (size_t)row * DHEAD + seg * 8);
        }
        #pragma unroll
        for (int i = 0; i < 4; ++i) {
            int e = tid + i * 256, row = e >> 3, seg = e & 7;
            cp16(bbase + (uint32_t)(buf * OUT_BH + row * HPAD + seg * 8) * 2u,
                 WOTh + (size_t)(n0 + row) * DMODEL + c * DHEAD + seg * 8);
        }
        asm volatile("cp.async.commit_group;");
    };

    issue(0, 0);
    for (int c = 0; c < 12; ++c) {
        const int buf = c & 1;
        if (c < 11) {
            issue(c + 1, buf ^ 1);
            asm volatile("cp.async.wait_group 1;");
        } else {
            asm volatile("cp.async.wait_group 0;");
        }
        __syncthreads();

        const __half* Ab = As + buf * OUT_AH;
        const __half* Bb = Bs + buf * OUT_BH;
        #pragma unroll
        for (int ks = 0; ks < 4; ++ks) {
            const int kb = ks * 16;
            uint32_t a[4][4];
            #pragma unroll
            for (int f = 0; f < 4; ++f) {
                const __half* r0 = Ab + (moff + f*16 + rA) * HPAD + kb + 2*cA;
                const __half* r1 = r0 + 8 * HPAD;
                a[f][0] = ldu32(r0);
                a[f][1] = ldu32(r1);
                a[f][2] = ldu32(r0 + 8);
                a[f][3] = ldu32(r1 + 8);
            }
            uint32_t b[4][2];
            #pragma unroll
            for (int j = 0; j < 4; ++j) {
                const __half* rb = Bb + (noff + j*8 + rA) * HPAD + kb + 2*cA;
                b[j][0] = ldu32(rb);
                b[j][1] = ldu32(rb + 8);
            }
            #pragma unroll
            for (int f = 0; f < 4; ++f)
                #pragma unroll
                for (int j = 0; j < 4; ++j)
                    mma_f16(acc[f][j], a[f], b[j]);
        }
        __syncthreads();
    }

    #pragma unroll
    for (int f = 0; f < 4; ++f) {
        #pragma unroll
        for (int j = 0; j < 4; ++j) {
            int col = n0 + noff + j*8 + 2*cA;
            float b0 = bo[col], b1 = bo[col + 1];
            int mrow = m0 + moff + f*16 + rA;
            *reinterpret_cast<float2*>(&out[(size_t)mrow * DMODEL + col]) =
                make_float2(acc[f][j][0] + b0, acc[f][j][1] + b1);
            *reinterpret_cast<float2*>(&out[(size_t)(mrow + 8) * DMODEL + col]) =
                make_float2(acc[f][j][2] + b0, acc[f][j][3] + b1);
        }
    }
}

// ---------------------------------------------------------------------------
extern "C" void kernel_launch(void* const* d_in, const int* in_sizes, int n_in,
                              void* d_out, int out_size)
{
    const float* x  = (const float*)d_in[0];
    const float* Wq = (const float*)d_in[1];
    const float* Wk = (const float*)d_in[2];
    const float* Wv = (const float*)d_in[3];
    const float* Wo = (const float*)d_in[4];
    const float* bq = (const float*)d_in[5];
    const float* bk = (const float*)d_in[6];
    const float* bv = (const float*)d_in[7];
    const float* bo = (const float*)d_in[8];
    float* out = (float*)d_out;

    cudaFuncSetAttribute(flash_f16, cudaFuncAttributeMaxDynamicSharedMemorySize, FLASH_SMEM);
    cudaFuncSetAttribute(qkv_f16,   cudaFuncAttributeMaxDynamicSharedMemorySize, QKV_SMEM);
    cudaFuncSetAttribute(out_f16,   cudaFuncAttributeMaxDynamicSharedMemorySize, OUT_SMEM);

    xh_kernel<<<MTOT*DMODEL/256, 256>>>(x);
    wth_kernel<<<NHEADS*3*DHEAD*DMODEL/256, 256>>>(Wq, Wk, Wv);
    woth_kernel<<<DMODEL*DMODEL/256, 256>>>(Wo);

    dim3 g1(MTOT/128, NHEADS);
    qkv_f16<<<g1, 256, QKV_SMEM>>>(bq, bk, bv);

    dim3 g2(SEQ/TQ, BATCH*NHEADS);
    flash_f16<<<g2, 256, FLASH_SMEM>>>();

    dim3 g3(MTOT/128, DMODEL/128);
    out_f16<<<g3, 256, OUT_SMEM>>>(bo, out);
}

// round 9
// speedup vs baseline: 9.5191x; 1.1403x over previous
#include <cuda_runtime.h>
#include <cuda_fp16.h>
#include <math_constants.h>
#include <cstdint>

// Problem dims
#define BATCH   2
#define SEQ     4096
#define DMODEL  768
#define NHEADS  12
#define DHEAD   64
#define MTOT    (BATCH*SEQ)          // 8192

// fp16 operand buffers
__device__ __half Xh[MTOT*DMODEL];
__device__ __half WTh[NHEADS*3*DHEAD*DMODEL];      // [h][mat*64+n][k]
__device__ __half WOTh[DMODEL*DMODEL];             // [d][hz]
__device__ __half Qh[BATCH*NHEADS*SEQ*DHEAD];      // pre-scaled by 1/8
__device__ __half Kh[BATCH*NHEADS*SEQ*DHEAD];
__device__ __half Vh[BATCH*NHEADS*SEQ*DHEAD];
__device__ __half Zh[BATCH*NHEADS*SEQ*DHEAD];

// ---------------------------------------------------------------------------
// helpers
// ---------------------------------------------------------------------------
__device__ __forceinline__ void mma_f16(float c[4], const uint32_t a[4], const uint32_t b[2]) {
    asm volatile(
        "mma.sync.aligned.m16n8k16.row.col.f32.f16.f16.f32 "
        "{%0,%1,%2,%3}, {%4,%5,%6,%7}, {%8,%9}, {%0,%1,%2,%3};"
        : "+f"(c[0]), "+f"(c[1]), "+f"(c[2]), "+f"(c[3])
        : "r"(a[0]), "r"(a[1]), "r"(a[2]), "r"(a[3]), "r"(b[0]), "r"(b[1]));
}

__device__ __forceinline__ void cp16(uint32_t dst, const void* src) {
    asm volatile("cp.async.cg.shared.global [%0], [%1], 16;" :: "r"(dst), "l"(src));
}

__device__ __forceinline__ uint32_t smem_u32(const void* p) {
    return (uint32_t)__cvta_generic_to_shared(p);
}

__device__ __forceinline__ uint32_t ldu32(const __half* p) {
    return *reinterpret_cast<const uint32_t*>(p);
}

__device__ __forceinline__ uint32_t h2bits(float x, float y) {
    __half2 v = __floats2half2_rn(x, y);
    return *reinterpret_cast<uint32_t*>(&v);
}

// ---------------------------------------------------------------------------
// Prologues
// ---------------------------------------------------------------------------
__global__ __launch_bounds__(256) void xh_kernel(const float4* __restrict__ x4)
{
    int i = blockIdx.x * 256 + threadIdx.x;
    float4 v = x4[i];
    uint2 o;
    o.x = h2bits(v.x, v.y);
    o.y = h2bits(v.z, v.w);
    reinterpret_cast<uint2*>(Xh)[i] = o;
}

// W[h][k][n] -> WTh[h*3*64 + mat*64 + n][k], tiled transpose
__global__ __launch_bounds__(256) void wth_kernel(
    const float* __restrict__ Wq, const float* __restrict__ Wk, const float* __restrict__ Wv)
{
    __shared__ float Ts[32][65];
    const int tid = threadIdx.x;
    const int kt  = blockIdx.x;            // 0..23
    const int mh  = blockIdx.y;            // 0..35 = h*3+mat
    const int mat = mh % 3, h = mh / 3;
    const float* W = (mat == 0 ? Wq : (mat == 1 ? Wk : Wv)) + (size_t)h * DMODEL * DHEAD;
    const int k0 = kt * 32;
    #pragma unroll
    for (int i = 0; i < 8; ++i) {
        int e = tid + i * 256, r = e >> 6, c = e & 63;
        Ts[r][c] = W[(size_t)(k0 + r) * DHEAD + c];
    }
    __syncthreads();
    #pragma unroll
    for (int i = 0; i < 8; ++i) {
        int e = tid + i * 256, n = e >> 5, kk = e & 31;
        WTh[((size_t)mh * 64 + n) * DMODEL + k0 + kk] = __float2half_rn(Ts[kk][n]);
    }
}

// Wo[hz][d] -> WOTh[d][hz], tiled transpose
__global__ __launch_bounds__(256) void woth_kernel(const float* __restrict__ Wo)
{
    __shared__ float Ts[32][33];
    const int tid = threadIdx.x;
    const int d0  = blockIdx.x * 32;
    const int z0  = blockIdx.y * 32;
    #pragma unroll
    for (int i = 0; i < 4; ++i) {
        int e = tid + i * 256, r = e >> 5, c = e & 31;
        Ts[r][c] = Wo[(size_t)(z0 + r) * DMODEL + d0 + c];
    }
    __syncthreads();
    #pragma unroll
    for (int i = 0; i < 4; ++i) {
        int e = tid + i * 256, r = e >> 5, c = e & 31;
        WOTh[(size_t)(d0 + r) * DMODEL + z0 + c] = __float2half_rn(Ts[c][r]);
    }
}

// ---------------------------------------------------------------------------
// Kernel 1: fused QKV projection. 512 thr (16 warps), warp tile 64x24.
// CTA tile M=128 x N=192, K-chunk 64. grid = (MTOT/128, 12)
// ---------------------------------------------------------------------------
#define HPAD 72
#define QKV_AH (128*HPAD)
#define QKV_BH (192*HPAD)
#define QKV_SMEM ((2*QKV_AH + 2*QKV_BH) * 2)   // 92160 B

__global__ __launch_bounds__(512) void qkv_f16(
    const float* __restrict__ bq, const float* __restrict__ bk, const float* __restrict__ bv)
{
    extern __shared__ __half hsm[];
    __half* As = hsm;
    __half* Bs = hsm + 2*QKV_AH;
    const uint32_t abase = smem_u32(As);
    const uint32_t bbase = smem_u32(Bs);

    const int m0  = blockIdx.x * 128;
    const int h   = blockIdx.y;
    const int tid = threadIdx.x;
    const int w    = tid >> 5;
    const int lane = tid & 31;
    const int rA   = lane >> 2;
    const int cA   = lane & 3;
    const int moff = (w >> 3) * 64;      // 0 or 64
    const int noff = (w & 7) * 24;       // 0..168

    const __half* Ag = Xh + (size_t)m0 * DMODEL;
    const __half* Bg = WTh + (size_t)h * 192 * DMODEL;

    float acc[4][3][4] = {};

    auto issue = [&](int c, int buf) {
        const int k0 = c * 64;
        #pragma unroll
        for (int i = 0; i < 2; ++i) {
            int e = tid + i * 512, row = e >> 3, seg = e & 7;
            cp16(abase + (uint32_t)(buf * QKV_AH + row * HPAD + seg * 8) * 2u,
                 Ag + (size_t)row * DMODEL + k0 + seg * 8);
        }
        #pragma unroll
        for (int i = 0; i < 3; ++i) {
            int e = tid + i * 512, row = e >> 3, seg = e & 7;
            cp16(bbase + (uint32_t)(buf * QKV_BH + row * HPAD + seg * 8) * 2u,
                 Bg + (size_t)row * DMODEL + k0 + seg * 8);
        }
        asm volatile("cp.async.commit_group;");
    };

    issue(0, 0);
    for (int c = 0; c < 12; ++c) {
        const int buf = c & 1;
        if (c < 11) {
            issue(c + 1, buf ^ 1);
            asm volatile("cp.async.wait_group 1;");
        } else {
            asm volatile("cp.async.wait_group 0;");
        }
        __syncthreads();

        const __half* Ab = As + buf * QKV_AH;
        const __half* Bb = Bs + buf * QKV_BH;
        #pragma unroll
        for (int ks = 0; ks < 4; ++ks) {
            const int kb = ks * 16;
            uint32_t a[4][4];
            #pragma unroll
            for (int f = 0; f < 4; ++f) {
                const __half* r0 = Ab + (moff + f*16 + rA) * HPAD + kb + 2*cA;
                const __half* r1 = r0 + 8 * HPAD;
                a[f][0] = ldu32(r0);
                a[f][1] = ldu32(r1);
                a[f][2] = ldu32(r0 + 8);
                a[f][3] = ldu32(r1 + 8);
            }
            uint32_t b[3][2];
            #pragma unroll
            for (int j = 0; j < 3; ++j) {
                const __half* rb = Bb + (noff + j*8 + rA) * HPAD + kb + 2*cA;
                b[j][0] = ldu32(rb);
                b[j][1] = ldu32(rb + 8);
            }
            #pragma unroll
            for (int f = 0; f < 4; ++f)
                #pragma unroll
                for (int j = 0; j < 3; ++j)
                    mma_f16(acc[f][j], a[f], b[j]);
        }
        __syncthreads();
    }

    const int bb = m0 / SEQ;
    const int s0 = m0 % SEQ;
    #pragma unroll
    for (int f = 0; f < 4; ++f) {
        #pragma unroll
        for (int j = 0; j < 3; ++j) {
            int gcol = noff + j*8 + 2*cA;
            int mat  = gcol >> 6;
            int z    = gcol & 63;
            const float* bias = (mat == 0 ? bq : (mat == 1 ? bk : bv)) + h * DHEAD;
            __half* Out = (mat == 0 ? Qh : (mat == 1 ? Kh : Vh));
            float sc = (mat == 0) ? 0.125f : 1.0f;
            float b0 = bias[z], b1 = bias[z + 1];
            int s = s0 + moff + f*16 + rA;
            __half* r0 = Out + ((size_t)(bb * NHEADS + h) * SEQ + s) * DHEAD + z;
            __half* r1 = r0 + 8 * DHEAD;
            *reinterpret_cast<uint32_t*>(r0) = h2bits((acc[f][j][0] + b0) * sc, (acc[f][j][1] + b1) * sc);
            *reinterpret_cast<uint32_t*>(r1) = h2bits((acc[f][j][2] + b0) * sc, (acc[f][j][3] + b1) * sc);
        }
    }
}

// ---------------------------------------------------------------------------
// Kernel 2: causal flash attention, fp16 mma, register-resident P,
// ldmatrix for K and V. 256 thr, TQ=128, TK=64, 2 CTAs/SM target.
// grid = (SEQ/TQ, B*H), heavy blocks first.
// ---------------------------------------------------------------------------
#define TQ 128
#define TK 64
#define KVH (TK*HPAD)
#define FLASH_SMEM (4*KVH*2)     // 36864 B (K + V, double buffered)

__global__ __launch_bounds__(256, 2) void flash_f16()
{
    extern __shared__ __half hsm[];
    __half* Ks = hsm;
    __half* Vs = hsm + 2*KVH;
    const uint32_t kbase = smem_u32(Ks);
    const uint32_t vbase = smem_u32(Vs);

    const int tid  = threadIdx.x;
    const int w    = tid >> 5;
    const int lane = tid & 31;
    const int rA   = lane >> 2;
    const int cA   = lane & 3;
    const int q0   = ((int)gridDim.x - 1 - (int)blockIdx.x) * TQ;
    const int bh   = blockIdx.y;

    // K ldmatrix lane addressing (x4: jt-pair block of 16 rows x 16 cols)
    const int ksel = lane >> 3;
    const int krow = (lane & 7) + ((ksel >> 1) << 3);   // 0..15
    const int kcol = (ksel & 1) << 3;                   // 0 or 8

    const __half* Qg = Qh + (size_t)(bh*SEQ + q0 + w*16) * DHEAD;
    const __half* Kg = Kh + (size_t)bh * SEQ * DHEAD;
    const __half* Vg = Vh + (size_t)bh * SEQ * DHEAD;

    uint32_t qf[4][4];
    #pragma unroll
    for (int ks = 0; ks < 4; ++ks) {
        const __half* r0 = Qg + rA * DHEAD + ks*16 + 2*cA;
        const __half* r1 = r0 + 8 * DHEAD;
        qf[ks][0] = ldu32(r0);
        qf[ks][1] = ldu32(r1);
        qf[ks][2] = ldu32(r0 + 8);
        qf[ks][3] = ldu32(r1 + 8);
    }

    float o[8][4];
    #pragma unroll
    for (int jt = 0; jt < 8; ++jt) { o[jt][0]=0.f; o[jt][1]=0.f; o[jt][2]=0.f; o[jt][3]=0.f; }
    float m0 = -CUDART_INF_F, m1 = -CUDART_INF_F;
    float l0 = 0.f, l1 = 0.f;

    const int ntiles = q0/TK + 2;

    auto issue = [&](int kt, int buf) {
        #pragma unroll
        for (int i = 0; i < 2; ++i) {
            int e = tid + i * 256, row = e >> 3, seg = e & 7;
            cp16(kbase + (uint32_t)(buf * KVH + row * HPAD + seg * 8) * 2u,
                 Kg + (size_t)(kt*TK + row) * DHEAD + seg * 8);
        }
        #pragma unroll
        for (int i = 0; i < 2; ++i) {
            int e = tid + i * 256, row = e >> 3, seg = e & 7;
            cp16(vbase + (uint32_t)(buf * KVH + row * HPAD + seg * 8) * 2u,
                 Vg + (size_t)(kt*TK + row) * DHEAD + seg * 8);
        }
        asm volatile("cp.async.commit_group;");
    };

    issue(0, 0);
    for (int kt = 0; kt < ntiles; ++kt) {
        const int buf = kt & 1;
        if (kt + 1 < ntiles) {
            issue(kt + 1, buf ^ 1);
            asm volatile("cp.async.wait_group 1;");
        } else {
            asm volatile("cp.async.wait_group 0;");
        }
        __syncthreads();

        if (kt*TK <= q0 + w*16 + 15) {
            const uint32_t kb2 = kbase + (uint32_t)(buf * KVH) * 2u;
            // S = Q @ K^T : 16x64, K frags via ldmatrix.x4
            float sc[8][4] = {};
            #pragma unroll
            for (int ks = 0; ks < 4; ++ks) {
                #pragma unroll
                for (int jtp = 0; jtp < 4; ++jtp) {
                    uint32_t addr = kb2 + (uint32_t)((jtp*16 + krow) * HPAD + ks*16 + kcol) * 2u;
                    uint32_t r0, r1, r2, r3;
                    asm volatile(
                        "ldmatrix.sync.aligned.m8n8.x4.shared.b16 {%0,%1,%2,%3}, [%4];"
                        : "=r"(r0), "=r"(r1), "=r"(r2), "=r"(r3) : "r"(addr));
                    uint32_t b0[2] = {r0, r1};
                    uint32_t b1[2] = {r2, r3};
                    mma_f16(sc[2*jtp    ], qf[ks], b0);
                    mma_f16(sc[2*jtp + 1], qf[ks], b1);
                }
            }

            if (kt >= ntiles - 2) {
                const int r0g = q0 + w*16 + rA;
                #pragma unroll
                for (int jt = 0; jt < 8; ++jt) {
                    int key = kt*TK + jt*8 + 2*cA;
                    if (key     > r0g    ) sc[jt][0] = -CUDART_INF_F;
                    if (key + 1 > r0g    ) sc[jt][1] = -CUDART_INF_F;
                    if (key     > r0g + 8) sc[jt][2] = -CUDART_INF_F;
                    if (key + 1 > r0g + 8) sc[jt][3] = -CUDART_INF_F;
                }
            }

            float rmax0 = fmaxf(sc[0][0], sc[0][1]), rmax1 = fmaxf(sc[0][2], sc[0][3]);
            #pragma unroll
            for (int jt = 1; jt < 8; ++jt) {
                rmax0 = fmaxf(rmax0, fmaxf(sc[jt][0], sc[jt][1]));
                rmax1 = fmaxf(rmax1, fmaxf(sc[jt][2], sc[jt][3]));
            }
            rmax0 = fmaxf(rmax0, __shfl_xor_sync(0xffffffffu, rmax0, 1));
            rmax0 = fmaxf(rmax0, __shfl_xor_sync(0xffffffffu, rmax0, 2));
            rmax1 = fmaxf(rmax1, __shfl_xor_sync(0xffffffffu, rmax1, 1));
            rmax1 = fmaxf(rmax1, __shfl_xor_sync(0xffffffffu, rmax1, 2));

            float mn0 = fmaxf(m0, rmax0);
            float mn1 = fmaxf(m1, rmax1);
            float f0 = __expf(m0 - mn0);
            float f1 = __expf(m1 - mn1);
            l0 *= f0; l1 *= f1;
            #pragma unroll
            for (int jt = 0; jt < 8; ++jt) {
                o[jt][0] *= f0; o[jt][1] *= f0;
                o[jt][2] *= f1; o[jt][3] *= f1;
            }

            // exp -> pack straight into PV A-fragments (C-layout == A-layout)
            uint32_t pa[4][4];
            #pragma unroll
            for (int jt = 0; jt < 8; ++jt) {
                float p0 = __expf(sc[jt][0] - mn0);
                float p1 = __expf(sc[jt][1] - mn0);
                float p2 = __expf(sc[jt][2] - mn1);
                float p3 = __expf(sc[jt][3] - mn1);
                l0 += p0 + p1;
                l1 += p2 + p3;
                pa[jt >> 1][(jt & 1) * 2 + 0] = h2bits(p0, p1);
                pa[jt >> 1][(jt & 1) * 2 + 1] = h2bits(p2, p3);
            }
            m0 = mn0; m1 = mn1;

            // O += P @ V via ldmatrix.x4.trans on V
            const uint32_t vb = vbase + (uint32_t)(buf * KVH) * 2u;
            #pragma unroll
            for (int kq = 0; kq < 4; ++kq) {
                #pragma unroll
                for (int jp = 0; jp < 4; ++jp) {
                    int lrow = kq*16 + (lane & 15);
                    int lcol = jp*16 + ((lane & 16) >> 1);
                    uint32_t addr = vb + (uint32_t)(lrow * HPAD + lcol) * 2u;
                    uint32_t r0, r1, r2, r3;
                    asm volatile(
                        "ldmatrix.sync.aligned.m8n8.x4.trans.shared.b16 {%0,%1,%2,%3}, [%4];"
                        : "=r"(r0), "=r"(r1), "=r"(r2), "=r"(r3) : "r"(addr));
                    uint32_t b0[2] = {r0, r1};
                    uint32_t b1[2] = {r2, r3};
                    mma_f16(o[2*jp    ], pa[kq], b0);
                    mma_f16(o[2*jp + 1], pa[kq], b1);
                }
            }
        }
        __syncthreads();
    }

    l0 += __shfl_xor_sync(0xffffffffu, l0, 1);
    l0 += __shfl_xor_sync(0xffffffffu, l0, 2);
    l1 += __shfl_xor_sync(0xffffffffu, l1, 1);
    l1 += __shfl_xor_sync(0xffffffffu, l1, 2);
    float inv0 = 1.f / l0;
    float inv1 = 1.f / l1;

    __half* Zp = Zh + (size_t)(bh*SEQ + q0 + w*16) * DHEAD;
    #pragma unroll
    for (int jt = 0; jt < 8; ++jt) {
        int col = jt*8 + 2*cA;
        *reinterpret_cast<uint32_t*>(Zp + rA * DHEAD + col) =
            h2bits(o[jt][0]*inv0, o[jt][1]*inv0);
        *reinterpret_cast<uint32_t*>(Zp + (rA + 8) * DHEAD + col) =
            h2bits(o[jt][2]*inv1, o[jt][3]*inv1);
    }
}

// ---------------------------------------------------------------------------
// Kernel 3: output projection. 512 thr (16 warps), warp tile 64x16.
// CTA 128x128, K-chunk 64. grid = (MTOT/128, 6)
// ---------------------------------------------------------------------------
#define OUT_AH (128*HPAD)
#define OUT_BH (128*HPAD)
#define OUT_SMEM ((2*OUT_AH + 2*OUT_BH) * 2)   // 73728 B

__global__ __launch_bounds__(512) void out_f16(
    const float* __restrict__ bo, float* __restrict__ out)
{
    extern __shared__ __half hsm[];
    __half* As = hsm;
    __half* Bs = hsm + 2*OUT_AH;
    const uint32_t abase = smem_u32(As);
    const uint32_t bbase = smem_u32(Bs);

    const int m0  = blockIdx.x * 128;
    const int n0  = blockIdx.y * 128;
    const int tid = threadIdx.x;
    const int w    = tid >> 5;
    const int lane = tid & 31;
    const int rA   = lane >> 2;
    const int cA   = lane & 3;
    const int moff = (w >> 3) * 64;
    const int noff = (w & 7) * 16;

    const int bb = m0 / SEQ;
    const int s0 = m0 % SEQ;

    float acc[4][2][4] = {};

    auto issue = [&](int c, int buf) {
        const __half* Ag = Zh + ((size_t)(bb * NHEADS + c) * SEQ + s0) * DHEAD;
        #pragma unroll
        for (int i = 0; i < 2; ++i) {
            int e = tid + i * 512, row = e >> 3, seg = e & 7;
            cp16(abase + (uint32_t)(buf * OUT_AH + row * HPAD + seg * 8) * 2u,
                 Ag + (size_t)row * DHEAD + seg * 8);
        }
        #pragma unroll
        for (int i = 0; i < 2; ++i) {
            int e = tid + i * 512, row = e >> 3, seg = e & 7;
            cp16(bbase + (uint32_t)(buf * OUT_BH + row * HPAD + seg * 8) * 2u,
                 WOTh + (size_t)(n0 + row) * DMODEL + c * DHEAD + seg * 8);
        }
        asm volatile("cp.async.commit_group;");
    };

    issue(0, 0);
    for (int c = 0; c < 12; ++c) {
        const int buf = c & 1;
        if (c < 11) {
            issue(c + 1, buf ^ 1);
            asm volatile("cp.async.wait_group 1;");
        } else {
            asm volatile("cp.async.wait_group 0;");
        }
        __syncthreads();

        const __half* Ab = As + buf * OUT_AH;
        const __half* Bb = Bs + buf * OUT_BH;
        #pragma unroll
        for (int ks = 0; ks < 4; ++ks) {
            const int kb = ks * 16;
            uint32_t a[4][4];
            #pragma unroll
            for (int f = 0; f < 4; ++f) {
                const __half* r0 = Ab + (moff + f*16 + rA) * HPAD + kb + 2*cA;
                const __half* r1 = r0 + 8 * HPAD;
                a[f][0] = ldu32(r0);
                a[f][1] = ldu32(r1);
                a[f][2] = ldu32(r0 + 8);
                a[f][3] = ldu32(r1 + 8);
            }
            uint32_t b[2][2];
            #pragma unroll
            for (int j = 0; j < 2; ++j) {
                const __half* rb = Bb + (noff + j*8 + rA) * HPAD + kb + 2*cA;
                b[j][0] = ldu32(rb);
                b[j][1] = ldu32(rb + 8);
            }
            #pragma unroll
            for (int f = 0; f < 4; ++f)
                #pragma unroll
                for (int j = 0; j < 2; ++j)
                    mma_f16(acc[f][j], a[f], b[j]);
        }
        __syncthreads();
    }

    #pragma unroll
    for (int f = 0; f < 4; ++f) {
        #pragma unroll
        for (int j = 0; j < 2; ++j) {
            int col = n0 + noff + j*8 + 2*cA;
            float b0 = bo[col], b1 = bo[col + 1];
            int mrow = m0 + moff + f*16 + rA;
            *reinterpret_cast<float2*>(&out[(size_t)mrow * DMODEL + col]) =
                make_float2(acc[f][j][0] + b0, acc[f][j][1] + b1);
            *reinterpret_cast<float2*>(&out[(size_t)(mrow + 8) * DMODEL + col]) =
                make_float2(acc[f][j][2] + b0, acc[f][j][3] + b1);
        }
    }
}

// ---------------------------------------------------------------------------
extern "C" void kernel_launch(void* const* d_in, const int* in_sizes, int n_in,
                              void* d_out, int out_size)
{
    const float* x  = (const float*)d_in[0];
    const float* Wq = (const float*)d_in[1];
    const float* Wk = (const float*)d_in[2];
    const float* Wv = (const float*)d_in[3];
    const float* Wo = (const float*)d_in[4];
    const float* bq = (const float*)d_in[5];
    const float* bk = (const float*)d_in[6];
    const float* bv = (const float*)d_in[7];
    const float* bo = (const float*)d_in[8];
    float* out = (float*)d_out;

    cudaFuncSetAttribute(flash_f16, cudaFuncAttributeMaxDynamicSharedMemorySize, FLASH_SMEM);
    cudaFuncSetAttribute(qkv_f16,   cudaFuncAttributeMaxDynamicSharedMemorySize, QKV_SMEM);
    cudaFuncSetAttribute(out_f16,   cudaFuncAttributeMaxDynamicSharedMemorySize, OUT_SMEM);

    xh_kernel<<<MTOT*DMODEL/1024, 256>>>((const float4*)x);
    dim3 gt1(DMODEL/32, 3*NHEADS);
    wth_kernel<<<gt1, 256>>>(Wq, Wk, Wv);
    dim3 gt2(DMODEL/32, DMODEL/32);
    woth_kernel<<<gt2, 256>>>(Wo);

    dim3 g1(MTOT/128, NHEADS);
    qkv_f16<<<g1, 512, QKV_SMEM>>>(bq, bk, bv);

    dim3 g2(SEQ/TQ, BATCH*NHEADS);
    flash_f16<<<g2, 256, FLASH_SMEM>>>();

    dim3 g3(MTOT/128, DMODEL/128);
    out_f16<<<g3, 512, OUT_SMEM>>>(bo, out);
}